// round 11
// baseline (speedup 1.0000x reference)
#include <cuda_runtime.h>
#include <math.h>

#define HW   4096
#define BB   16
#define CC   192
#define HEADS 6
#define DD   32
#define HID  768
#define NPAIR 96

// ---------------- scratch (device globals; no allocation APIs) ----------------
__device__ float g_x   [(size_t)BB*CC*HW];
__device__ float g_y   [(size_t)BB*CC*HW];
__device__ float g_act [(size_t)BB*CC*HW];
__device__ float g_t   [(size_t)BB*CC*HW];
__device__ float g_qk  [(size_t)BB*2*CC*HW];
__device__ float g_q   [(size_t)BB*CC*HW];
__device__ float g_qr  [(size_t)BB*CC*HW];
__device__ float g_kr  [(size_t)BB*CC*HW];
__device__ float g_attn[(size_t)BB*CC*HW];
__device__ float g_h   [(size_t)BB*HID*HW];
__device__ float g_kv  [BB*HEADS*DD*DD];
__device__ float g_km  [BB*CC];
__device__ float g_cos [NPAIR*HW];
__device__ float g_sin [NPAIR*HW];

// ---------------- RoPE tables (double math to match numpy fp64 -> fp32) -------
__global__ void rope_init_kernel() {
    int idx = blockIdx.x * 256 + threadIdx.x;
    if (idx >= NPAIR * HW) return;
    int p   = idx / HW;
    int pix = idx % HW;
    int h = pix >> 6, w = pix & 63;
    int j   = (p < 48) ? p : p - 48;
    int pos = (p < 48) ? h : w;
    double theta = pow(10000.0, -(double)j / 48.0);
    double ang = (double)pos * theta;
    g_cos[idx] = (float)cos(ang);
    g_sin[idx] = (float)sin(ang);
}

// ---------------- depthwise 3x3 ------------------------------------------------
// MODE 1: out = add + dw(in)          (cpe residual; in-place safe)
// MODE 2: out = silu(dw(in))          (dwc; in-place safe)
// MODE 3: out = (add + dw(in)) * gate (lepe + output gate)
template <int MODE>
__global__ __launch_bounds__(256) void dw_kernel(
    const float* __restrict__ in, const float* __restrict__ wt,
    const float* __restrict__ bs, const float* __restrict__ add,
    const float* __restrict__ gate, float* __restrict__ out)
{
    __shared__ float sp[HW];
    int bc = blockIdx.x;
    int c  = bc % CC;
    const float* ip = in + (size_t)bc * HW;
    int t = threadIdx.x;
#pragma unroll
    for (int i = 0; i < 16; i++) sp[t + i * 256] = ip[t + i * 256];
    float w[9];
#pragma unroll
    for (int i = 0; i < 9; i++) w[i] = wt[c * 9 + i];
    float bb = bs[c];
    __syncthreads();
    for (int i = t; i < HW; i += 256) {
        int y = i >> 6, x = i & 63;
        float s = bb;
#pragma unroll
        for (int ki = 0; ki < 3; ki++) {
            int yy = y + ki - 1;
            if ((unsigned)yy < 64u) {
#pragma unroll
                for (int kj = 0; kj < 3; kj++) {
                    int xx = x + kj - 1;
                    if ((unsigned)xx < 64u) s += w[ki * 3 + kj] * sp[yy * 64 + xx];
                }
            }
        }
        size_t o = (size_t)bc * HW + i;
        if (MODE == 1)      out[o] = add[o] + s;
        else if (MODE == 2) out[o] = s / (1.f + expf(-s));
        else                out[o] = (add[o] + s) * gate[o];
    }
}

// ---------------- LayerNorm over channels (per pixel) --------------------------
__global__ __launch_bounds__(256) void ln_kernel(
    const float* __restrict__ in, const float* __restrict__ w,
    const float* __restrict__ b, float* __restrict__ out)
{
    int bi  = blockIdx.y;
    int pix = blockIdx.x * 256 + threadIdx.x;
    const float* ip = in + (size_t)bi * CC * HW + pix;
    float s = 0.f, s2 = 0.f;
#pragma unroll 4
    for (int c = 0; c < CC; c++) { float v = ip[(size_t)c * HW]; s += v; s2 += v * v; }
    float mu  = s * (1.f / CC);
    float var = s2 * (1.f / CC) - mu * mu;
    float r   = rsqrtf(var + 1e-5f);
    float* op = out + (size_t)bi * CC * HW + pix;
#pragma unroll 4
    for (int c = 0; c < CC; c++)
        op[(size_t)c * HW] = (ip[(size_t)c * HW] - mu) * r * w[c] + b[c];
}

// ---------------- conv1x1 = GEMM: out[b,o,p] = act(sum_c W[o,c] in[b,c,p] + bias) (+res)
// ACT: 0 none, 1 silu, 2 gelu(exact). Tile 64(M) x 64(N) x 16(K), 256 threads, 4x4/thread.
template <int ACT, bool RES>
__global__ __launch_bounds__(256) void gemm_kernel(
    const float* __restrict__ in, const float* __restrict__ Wm,
    const float* __restrict__ bias, const float* __restrict__ res,
    float* __restrict__ out, int Cin, int Cout)
{
    __shared__ float As[16][64];   // [k][m]
    __shared__ float Bs[16][64];   // [k][n]
    const int b  = blockIdx.z;
    const int mb = blockIdx.y * 64, nb = blockIdx.x * 64;
    const int t  = threadIdx.x;
    const int tx = t & 15, ty = t >> 4;
    const float* inb = in + (size_t)b * Cin * HW;
    float acc[4][4];
#pragma unroll
    for (int i = 0; i < 4; i++)
#pragma unroll
        for (int j = 0; j < 4; j++) acc[i][j] = 0.f;

    const int mA = t >> 2, kqA = (t & 3) << 2;
    const int kB = t >> 4, nqB = (t & 15) << 2;

    for (int k0 = 0; k0 < Cin; k0 += 16) {
        float4 wv = *(const float4*)(Wm + (size_t)(mb + mA) * Cin + k0 + kqA);
        As[kqA + 0][mA] = wv.x; As[kqA + 1][mA] = wv.y;
        As[kqA + 2][mA] = wv.z; As[kqA + 3][mA] = wv.w;
        float4 xv = *(const float4*)(inb + (size_t)(k0 + kB) * HW + nb + nqB);
        *(float4*)(&Bs[kB][nqB]) = xv;
        __syncthreads();
#pragma unroll
        for (int kk = 0; kk < 16; kk++) {
            float4 a  = *(const float4*)(&As[kk][ty << 2]);
            float4 bv = *(const float4*)(&Bs[kk][tx << 2]);
            acc[0][0] += a.x * bv.x; acc[0][1] += a.x * bv.y; acc[0][2] += a.x * bv.z; acc[0][3] += a.x * bv.w;
            acc[1][0] += a.y * bv.x; acc[1][1] += a.y * bv.y; acc[1][2] += a.y * bv.z; acc[1][3] += a.y * bv.w;
            acc[2][0] += a.z * bv.x; acc[2][1] += a.z * bv.y; acc[2][2] += a.z * bv.z; acc[2][3] += a.z * bv.w;
            acc[3][0] += a.w * bv.x; acc[3][1] += a.w * bv.y; acc[3][2] += a.w * bv.z; acc[3][3] += a.w * bv.w;
        }
        __syncthreads();
    }
#pragma unroll
    for (int i = 0; i < 4; i++) {
        int m = mb + (ty << 2) + i;
        float bi = bias[m];
        size_t off = ((size_t)b * Cout + m) * HW + nb + (tx << 2);
        float* op = out + off;
        const float* rp = res + off;
#pragma unroll
        for (int j = 0; j < 4; j++) {
            float v = acc[i][j] + bi;
            if (ACT == 1) v = v / (1.f + expf(-v));
            if (ACT == 2) v = 0.5f * v * (1.f + erff(v * 0.70710678118654752f));
            if (RES) v += rp[j];
            op[j] = v;
        }
    }
}

// ---------------- elu+1, RoPE(q,k), kmean --------------------------------------
__global__ __launch_bounds__(256) void qkpost_kernel() {
    int b = blockIdx.y, p = blockIdx.x;         // p: channel pair 0..95
    int c0 = 2 * p;
    const float* qp0 = g_qk + ((size_t)b * 2 * CC + c0) * HW;
    const float* qp1 = qp0 + HW;
    const float* kp0 = g_qk + ((size_t)b * 2 * CC + CC + c0) * HW;
    const float* kp1 = kp0 + HW;
    size_t o0 = ((size_t)b * CC + c0) * HW;
    const float* cb = g_cos + (size_t)p * HW;
    const float* sb = g_sin + (size_t)p * HW;
    float sk0 = 0.f, sk1 = 0.f;
    for (int i = threadIdx.x; i < HW; i += 256) {
        float qa = qp0[i]; qa = (qa > 0.f) ? qa + 1.f : expf(qa);
        float qb = qp1[i]; qb = (qb > 0.f) ? qb + 1.f : expf(qb);
        float ka = kp0[i]; ka = (ka > 0.f) ? ka + 1.f : expf(ka);
        float kb = kp1[i]; kb = (kb > 0.f) ? kb + 1.f : expf(kb);
        float cs = cb[i], sn = sb[i];
        g_q[o0 + i]       = qa;
        g_q[o0 + HW + i]  = qb;
        g_qr[o0 + i]      = qa * cs - qb * sn;
        g_qr[o0 + HW + i] = qa * sn + qb * cs;
        g_kr[o0 + i]      = ka * cs - kb * sn;
        g_kr[o0 + HW + i] = ka * sn + kb * cs;
        sk0 += ka; sk1 += kb;
    }
    __shared__ float r0[256], r1[256];
    int t = threadIdx.x;
    r0[t] = sk0; r1[t] = sk1;
    __syncthreads();
    for (int s = 128; s > 0; s >>= 1) {
        if (t < s) { r0[t] += r0[t + s]; r1[t] += r1[t + s]; }
        __syncthreads();
    }
    if (t == 0) {
        g_km[b * CC + c0]     = r0[0] * (1.f / HW);
        g_km[b * CC + c0 + 1] = r1[0] * (1.f / HW);
    }
}

// ---------------- kv[b,h,d,e] = (1/n) sum_n k_rope[n,d] v[n,e] -----------------
__global__ __launch_bounds__(256) void kv_kernel() {
    int h = blockIdx.x, b = blockIdx.y;
    __shared__ float ks[64][36];   // [nn][d]
    __shared__ float vs[64][33];   // [nn][e]
    const float* kp = g_kr + ((size_t)b * CC + h * DD) * HW;
    const float* vp = g_t  + ((size_t)b * CC + h * DD) * HW;
    int t = threadIdx.x;
    int e = t & 31, d0 = (t >> 5) * 4;
    float a0 = 0.f, a1 = 0.f, a2 = 0.f, a3 = 0.f;
    for (int n0 = 0; n0 < HW; n0 += 64) {
#pragma unroll
        for (int l = 0; l < 8; l++) {
            int i  = t + l * 256;
            int dd = i >> 6, nn = i & 63;
            ks[nn][dd] = kp[(size_t)dd * HW + n0 + nn];
            vs[nn][dd] = vp[(size_t)dd * HW + n0 + nn];
        }
        __syncthreads();
#pragma unroll 4
        for (int nn = 0; nn < 64; nn++) {
            float4 kk = *(const float4*)&ks[nn][d0];
            float  vv = vs[nn][e];
            a0 += kk.x * vv; a1 += kk.y * vv; a2 += kk.z * vv; a3 += kk.w * vv;
        }
        __syncthreads();
    }
    float sc = 1.f / HW;
    int base = ((b * HEADS + h) * DD + d0) * DD + e;
    g_kv[base]          = a0 * sc;
    g_kv[base + DD]     = a1 * sc;
    g_kv[base + 2 * DD] = a2 * sc;
    g_kv[base + 3 * DD] = a3 * sc;
}

// ---------------- attn[b,h,n,e] = z * sum_d q_rope[n,d] kv[d,e] ----------------
__global__ __launch_bounds__(256) void attn_kernel() {
    int tile = blockIdx.x, h = blockIdx.y, b = blockIdx.z;
    __shared__ float kvs[DD * DD];
    __shared__ float km[DD];
    int t = threadIdx.x;
#pragma unroll
    for (int l = 0; l < 4; l++)
        kvs[t + l * 256] = g_kv[(b * HEADS + h) * DD * DD + t + l * 256];
    if (t < DD) km[t] = g_km[b * CC + h * DD + t];
    __syncthreads();
    int pix = tile * 256 + t;
    const float* qp  = g_q  + ((size_t)b * CC + h * DD) * HW + pix;
    const float* qrp = g_qr + ((size_t)b * CC + h * DD) * HW + pix;
    float s = 0.f;
#pragma unroll
    for (int d = 0; d < DD; d++) s += qp[(size_t)d * HW] * km[d];
    float z = 1.f / (s + 1e-6f);
    float acc[DD];
#pragma unroll
    for (int e2 = 0; e2 < DD; e2++) acc[e2] = 0.f;
#pragma unroll 8
    for (int d = 0; d < DD; d++) {
        float qd = qrp[(size_t)d * HW];
#pragma unroll
        for (int e2 = 0; e2 < DD; e2++) acc[e2] += qd * kvs[d * DD + e2];
    }
    float* op = g_attn + ((size_t)b * CC + h * DD) * HW + pix;
#pragma unroll
    for (int e2 = 0; e2 < DD; e2++) op[(size_t)e2 * HW] = acc[e2] * z;
}

// ---------------- host ----------------------------------------------------------
extern "C" void kernel_launch(void* const* d_in, const int* in_sizes, int n_in,
                              void* d_out, int out_size)
{
    const float* x      = (const float*)d_in[0];
    const float* cpe1_w = (const float*)d_in[1];
    const float* cpe1_b = (const float*)d_in[2];
    const float* n1_w   = (const float*)d_in[3];
    const float* n1_b   = (const float*)d_in[4];
    const float* ap_w   = (const float*)d_in[5];
    const float* ap_b   = (const float*)d_in[6];
    const float* ip_w   = (const float*)d_in[7];
    const float* ip_b   = (const float*)d_in[8];
    const float* dwc_w  = (const float*)d_in[9];
    const float* dwc_b  = (const float*)d_in[10];
    const float* qkw    = (const float*)d_in[11];
    const float* qkb    = (const float*)d_in[12];
    const float* lepe_w = (const float*)d_in[13];
    const float* lepe_b = (const float*)d_in[14];
    const float* op_w   = (const float*)d_in[15];
    const float* op_b   = (const float*)d_in[16];
    const float* cpe2_w = (const float*)d_in[17];
    const float* cpe2_b = (const float*)d_in[18];
    const float* n2_w   = (const float*)d_in[19];
    const float* n2_b   = (const float*)d_in[20];
    const float* fc1_w  = (const float*)d_in[21];
    const float* fc1_b  = (const float*)d_in[22];
    const float* fc2_w  = (const float*)d_in[23];
    const float* fc2_b  = (const float*)d_in[24];
    float* out = (float*)d_out;

    void* tmp;
    cudaGetSymbolAddress(&tmp, g_x);    float* px    = (float*)tmp;
    cudaGetSymbolAddress(&tmp, g_y);    float* py    = (float*)tmp;
    cudaGetSymbolAddress(&tmp, g_act);  float* pact  = (float*)tmp;
    cudaGetSymbolAddress(&tmp, g_t);    float* pt    = (float*)tmp;
    cudaGetSymbolAddress(&tmp, g_qk);   float* pqk   = (float*)tmp;
    cudaGetSymbolAddress(&tmp, g_attn); float* pattn = (float*)tmp;
    cudaGetSymbolAddress(&tmp, g_h);    float* ph    = (float*)tmp;

    // RoPE tables (deterministic, cheap; recomputed every replay)
    rope_init_kernel<<<(NPAIR * HW + 255) / 256, 256>>>();

    // x = x + cpe1(x)
    dw_kernel<1><<<BB * CC, 256>>>(x, cpe1_w, cpe1_b, x, nullptr, px);

    // y = norm1(x)
    ln_kernel<<<dim3(HW / 256, BB), 256>>>(px, n1_w, n1_b, py);

    // act_res = silu(act_proj(y));  t0 = in_proj(y)
    gemm_kernel<1, false><<<dim3(HW / 64, CC / 64, BB), 256>>>(py, ap_w, ap_b, nullptr, pact, CC, CC);
    gemm_kernel<0, false><<<dim3(HW / 64, CC / 64, BB), 256>>>(py, ip_w, ip_b, nullptr, pt,   CC, CC);

    // t = silu(dwc(t0))   (in-place, plane staged in smem)
    dw_kernel<2><<<BB * CC, 256>>>(pt, dwc_w, dwc_b, nullptr, nullptr, pt);

    // qk = qk_w @ t + qk_b
    gemm_kernel<0, false><<<dim3(HW / 64, 2 * CC / 64, BB), 256>>>(pt, qkw, qkb, nullptr, pqk, CC, 2 * CC);

    // q = elu+1, k = elu+1, rope(q), rope(k), kmean
    qkpost_kernel<<<dim3(NPAIR, BB), 256>>>();

    // kv = (1/n) k_rope^T v ; attn = z * q_rope kv
    kv_kernel<<<dim3(HEADS, BB), 256>>>();
    attn_kernel<<<dim3(HW / 256, HEADS, BB), 256>>>();

    // gated = (attn + lepe(v)) * act_res
    dw_kernel<3><<<BB * CC, 256>>>(pt, lepe_w, lepe_b, pattn, pact, pattn);

    // x = x + out_proj(gated)
    gemm_kernel<0, true><<<dim3(HW / 64, CC / 64, BB), 256>>>(pattn, op_w, op_b, px, px, CC, CC);

    // x = x + cpe2(x)
    dw_kernel<1><<<BB * CC, 256>>>(px, cpe2_w, cpe2_b, px, nullptr, px);

    // MLP: out = x + fc2(gelu(fc1(norm2(x))))
    ln_kernel<<<dim3(HW / 256, BB), 256>>>(px, n2_w, n2_b, py);
    gemm_kernel<2, false><<<dim3(HW / 64, HID / 64, BB), 256>>>(py, fc1_w, fc1_b, nullptr, ph, CC, HID);
    gemm_kernel<0, true><<<dim3(HW / 64, CC / 64, BB), 256>>>(ph, fc2_w, fc2_b, px, out, HID, CC);
}

// round 13
// speedup vs baseline: 1.4172x; 1.4172x over previous
#include <cuda_runtime.h>
#include <cstdint>
#include <math.h>

#define HW   4096
#define BB   16
#define CC   192
#define HEADS 6
#define DD   32
#define HID  768
#define NPAIR 96

// ---------------- scratch (device globals; no allocation APIs) ----------------
__device__ float g_x   [(size_t)BB*CC*HW];
__device__ float g_y   [(size_t)BB*CC*HW];
__device__ float g_act [(size_t)BB*CC*HW];
__device__ float g_t   [(size_t)BB*CC*HW];
__device__ float g_qk  [(size_t)BB*2*CC*HW];
__device__ float g_q   [(size_t)BB*CC*HW];
__device__ float g_qr  [(size_t)BB*CC*HW];
__device__ float g_kr  [(size_t)BB*CC*HW];
__device__ float g_attn[(size_t)BB*CC*HW];
__device__ float g_h   [(size_t)BB*HID*HW];
__device__ float g_kv  [BB*HEADS*DD*DD];
__device__ float g_km  [BB*CC];
__device__ float g_cos [NPAIR*HW];
__device__ float g_sin [NPAIR*HW];

// ---------------- RoPE tables (double math to match numpy fp64 -> fp32) -------
__global__ void rope_init_kernel() {
    int idx = blockIdx.x * 256 + threadIdx.x;
    if (idx >= NPAIR * HW) return;
    int p   = idx / HW;
    int pix = idx % HW;
    int h = pix >> 6, w = pix & 63;
    int j   = (p < 48) ? p : p - 48;
    int pos = (p < 48) ? h : w;
    double theta = pow(10000.0, -(double)j / 48.0);
    double ang = (double)pos * theta;
    g_cos[idx] = (float)cos(ang);
    g_sin[idx] = (float)sin(ang);
}

// ---------------- depthwise 3x3 ------------------------------------------------
// MODE 1: out = add + dw(in)          MODE 2: out = silu(dw(in))
// MODE 3: out = (add + dw(in)) * gate
template <int MODE>
__global__ __launch_bounds__(256) void dw_kernel(
    const float* __restrict__ in, const float* __restrict__ wt,
    const float* __restrict__ bs, const float* __restrict__ add,
    const float* __restrict__ gate, float* __restrict__ out)
{
    __shared__ float sp[HW];
    int bc = blockIdx.x;
    int c  = bc % CC;
    const float* ip = in + (size_t)bc * HW;
    int t = threadIdx.x;
#pragma unroll
    for (int i = 0; i < 16; i++) sp[t + i * 256] = ip[t + i * 256];
    float w[9];
#pragma unroll
    for (int i = 0; i < 9; i++) w[i] = wt[c * 9 + i];
    float bb = bs[c];
    __syncthreads();
    for (int i = t; i < HW; i += 256) {
        int y = i >> 6, x = i & 63;
        float s = bb;
#pragma unroll
        for (int ki = 0; ki < 3; ki++) {
            int yy = y + ki - 1;
            if ((unsigned)yy < 64u) {
#pragma unroll
                for (int kj = 0; kj < 3; kj++) {
                    int xx = x + kj - 1;
                    if ((unsigned)xx < 64u) s += w[ki * 3 + kj] * sp[yy * 64 + xx];
                }
            }
        }
        size_t o = (size_t)bc * HW + i;
        if (MODE == 1)      out[o] = add[o] + s;
        else if (MODE == 2) out[o] = s / (1.f + expf(-s));
        else                out[o] = (add[o] + s) * gate[o];
    }
}

// ---------------- LayerNorm over channels (per pixel) --------------------------
__global__ __launch_bounds__(256) void ln_kernel(
    const float* __restrict__ in, const float* __restrict__ w,
    const float* __restrict__ b, float* __restrict__ out)
{
    int bi  = blockIdx.y;
    int pix = blockIdx.x * 256 + threadIdx.x;
    const float* ip = in + (size_t)bi * CC * HW + pix;
    float s = 0.f, s2 = 0.f;
#pragma unroll 4
    for (int c = 0; c < CC; c++) { float v = ip[(size_t)c * HW]; s += v; s2 += v * v; }
    float mu  = s * (1.f / CC);
    float var = s2 * (1.f / CC) - mu * mu;
    float r   = rsqrtf(var + 1e-5f);
    float* op = out + (size_t)bi * CC * HW + pix;
#pragma unroll 4
    for (int c = 0; c < CC; c++)
        op[(size_t)c * HW] = (ip[(size_t)c * HW] - mu) * r * w[c] + b[c];
}

// ---------------- tf32 helpers --------------------------------------------------
__device__ __forceinline__ float f2tf(float x) {
    unsigned u;
    asm("cvt.rna.tf32.f32 %0, %1;" : "=r"(u) : "f"(x));
    return __uint_as_float(u);
}
__device__ __forceinline__ void mma_tf32(float* c, const unsigned* a, const unsigned* b) {
    asm volatile(
        "mma.sync.aligned.m16n8k8.row.col.f32.tf32.tf32.f32 "
        "{%0,%1,%2,%3}, {%4,%5,%6,%7}, {%8,%9}, {%0,%1,%2,%3};\n"
        : "+f"(c[0]), "+f"(c[1]), "+f"(c[2]), "+f"(c[3])
        : "r"(a[0]), "r"(a[1]), "r"(a[2]), "r"(a[3]), "r"(b[0]), "r"(b[1]));
}

// ---------------- conv1x1 GEMM on tensor cores (tf32) ---------------------------
// out[b,m,p] = act(sum_c W[m,c] in[b,c,p] + bias[m]) (+res)
// Block tile 64(M) x 128(N) x 32(K); 8 warps in 2x4, warp tile 32x32;
// m16n8k8 tf32 mma; register-prefetch double pipeline on gmem loads.
template <int ACT, bool RES>
__global__ __launch_bounds__(256) void gemm_tc(
    const float* __restrict__ in, const float* __restrict__ Wm,
    const float* __restrict__ bias, const float* __restrict__ res,
    float* __restrict__ out, int Cin, int Cout)
{
    __shared__ float As[64][36];    // [m][k], pad 36 -> conflict-free frag loads
    __shared__ float Bs[32][132];   // [k][n], pad 132

    const int b  = blockIdx.z;
    const int mb = blockIdx.y * 64, nb = blockIdx.x * 128;
    const int t  = threadIdx.x;
    const int w  = t >> 5, lane = t & 31;
    const int g  = lane >> 2, tq = lane & 3;
    const int wm = (w >> 2) * 32, wn = (w & 3) * 32;

    const float* inb = in + (size_t)b * Cin * HW;
    // A loader: thread t handles W row (mb + t/4), k-span (t%4)*8 .. +7
    const int amr = t >> 2, akk = (t & 3) * 8;
    const float* wp = Wm + (size_t)(mb + amr) * Cin + akk;
    // B loader: thread t handles k-row t/8, n-span (t%8)*16 .. +15
    const int bkr = t >> 3, bnn = (t & 7) * 16;
    const float* xp = inb + (size_t)bkr * HW + nb + bnn;

    float c[2][4][4];
#pragma unroll
    for (int i = 0; i < 2; i++)
#pragma unroll
        for (int j = 0; j < 4; j++)
#pragma unroll
            for (int q = 0; q < 4; q++) c[i][j][q] = 0.f;

    float4 pa0, pa1, pb0, pb1, pb2, pb3;
    // prologue: load chunk 0
    pa0 = *(const float4*)(wp);
    pa1 = *(const float4*)(wp + 4);
    pb0 = *(const float4*)(xp);
    pb1 = *(const float4*)(xp + 4);
    pb2 = *(const float4*)(xp + 8);
    pb3 = *(const float4*)(xp + 12);

    const int nchunk = Cin >> 5;
    for (int ch = 0; ch < nchunk; ch++) {
        // store current chunk (convert to tf32)
        {
            float4 v;
            v.x = f2tf(pa0.x); v.y = f2tf(pa0.y); v.z = f2tf(pa0.z); v.w = f2tf(pa0.w);
            *(float4*)(&As[amr][akk]) = v;
            v.x = f2tf(pa1.x); v.y = f2tf(pa1.y); v.z = f2tf(pa1.z); v.w = f2tf(pa1.w);
            *(float4*)(&As[amr][akk + 4]) = v;
            v.x = f2tf(pb0.x); v.y = f2tf(pb0.y); v.z = f2tf(pb0.z); v.w = f2tf(pb0.w);
            *(float4*)(&Bs[bkr][bnn]) = v;
            v.x = f2tf(pb1.x); v.y = f2tf(pb1.y); v.z = f2tf(pb1.z); v.w = f2tf(pb1.w);
            *(float4*)(&Bs[bkr][bnn + 4]) = v;
            v.x = f2tf(pb2.x); v.y = f2tf(pb2.y); v.z = f2tf(pb2.z); v.w = f2tf(pb2.w);
            *(float4*)(&Bs[bkr][bnn + 8]) = v;
            v.x = f2tf(pb3.x); v.y = f2tf(pb3.y); v.z = f2tf(pb3.z); v.w = f2tf(pb3.w);
            *(float4*)(&Bs[bkr][bnn + 12]) = v;
        }
        __syncthreads();
        // prefetch next chunk while computing this one
        if (ch + 1 < nchunk) {
            int k0 = (ch + 1) << 5;
            pa0 = *(const float4*)(wp + k0);
            pa1 = *(const float4*)(wp + k0 + 4);
            const float* xq = xp + (size_t)k0 * HW;
            pb0 = *(const float4*)(xq);
            pb1 = *(const float4*)(xq + 4);
            pb2 = *(const float4*)(xq + 8);
            pb3 = *(const float4*)(xq + 12);
        }
#pragma unroll
        for (int ks = 0; ks < 4; ks++) {
            const int k8 = ks * 8;
            unsigned a[2][4], bf[4][2];
#pragma unroll
            for (int i = 0; i < 2; i++) {
                int m0 = wm + i * 16 + g;
                a[i][0] = __float_as_uint(As[m0][k8 + tq]);
                a[i][1] = __float_as_uint(As[m0 + 8][k8 + tq]);
                a[i][2] = __float_as_uint(As[m0][k8 + tq + 4]);
                a[i][3] = __float_as_uint(As[m0 + 8][k8 + tq + 4]);
            }
#pragma unroll
            for (int j = 0; j < 4; j++) {
                int n0 = wn + j * 8 + g;
                bf[j][0] = __float_as_uint(Bs[k8 + tq][n0]);
                bf[j][1] = __float_as_uint(Bs[k8 + tq + 4][n0]);
            }
#pragma unroll
            for (int i = 0; i < 2; i++)
#pragma unroll
                for (int j = 0; j < 4; j++) mma_tf32(c[i][j], a[i], bf[j]);
        }
        __syncthreads();
    }

    // epilogue: c layout -> rows (g, g+8), cols (tq*2, tq*2+1)
#pragma unroll
    for (int i = 0; i < 2; i++) {
#pragma unroll
        for (int rh = 0; rh < 2; rh++) {
            int m = mb + wm + i * 16 + g + rh * 8;
            float bi = bias[m];
            size_t rowoff = ((size_t)b * Cout + m) * HW + nb;
#pragma unroll
            for (int j = 0; j < 4; j++) {
                int n = wn + j * 8 + tq * 2;
                float v0 = c[i][j][rh * 2 + 0] + bi;
                float v1 = c[i][j][rh * 2 + 1] + bi;
                if (ACT == 1) { v0 = v0 / (1.f + expf(-v0)); v1 = v1 / (1.f + expf(-v1)); }
                if (ACT == 2) {
                    v0 = 0.5f * v0 * (1.f + erff(v0 * 0.70710678118654752f));
                    v1 = 0.5f * v1 * (1.f + erff(v1 * 0.70710678118654752f));
                }
                if (RES) {
                    const float* rp = res + rowoff + n;
                    v0 += rp[0]; v1 += rp[1];
                }
                float2 vv = make_float2(v0, v1);
                *(float2*)(out + rowoff + n) = vv;
            }
        }
    }
}

// ---------------- elu+1, RoPE(q,k), kmean --------------------------------------
__global__ __launch_bounds__(256) void qkpost_kernel() {
    int b = blockIdx.y, p = blockIdx.x;         // p: channel pair 0..95
    int c0 = 2 * p;
    const float* qp0 = g_qk + ((size_t)b * 2 * CC + c0) * HW;
    const float* qp1 = qp0 + HW;
    const float* kp0 = g_qk + ((size_t)b * 2 * CC + CC + c0) * HW;
    const float* kp1 = kp0 + HW;
    size_t o0 = ((size_t)b * CC + c0) * HW;
    const float* cb = g_cos + (size_t)p * HW;
    const float* sb = g_sin + (size_t)p * HW;
    float sk0 = 0.f, sk1 = 0.f;
    for (int i = threadIdx.x; i < HW; i += 256) {
        float qa = qp0[i]; qa = (qa > 0.f) ? qa + 1.f : expf(qa);
        float qb = qp1[i]; qb = (qb > 0.f) ? qb + 1.f : expf(qb);
        float ka = kp0[i]; ka = (ka > 0.f) ? ka + 1.f : expf(ka);
        float kb = kp1[i]; kb = (kb > 0.f) ? kb + 1.f : expf(kb);
        float cs = cb[i], sn = sb[i];
        g_q[o0 + i]       = qa;
        g_q[o0 + HW + i]  = qb;
        g_qr[o0 + i]      = qa * cs - qb * sn;
        g_qr[o0 + HW + i] = qa * sn + qb * cs;
        g_kr[o0 + i]      = ka * cs - kb * sn;
        g_kr[o0 + HW + i] = ka * sn + kb * cs;
        sk0 += ka; sk1 += kb;
    }
    __shared__ float r0[256], r1[256];
    int t = threadIdx.x;
    r0[t] = sk0; r1[t] = sk1;
    __syncthreads();
    for (int s = 128; s > 0; s >>= 1) {
        if (t < s) { r0[t] += r0[t + s]; r1[t] += r1[t + s]; }
        __syncthreads();
    }
    if (t == 0) {
        g_km[b * CC + c0]     = r0[0] * (1.f / HW);
        g_km[b * CC + c0 + 1] = r1[0] * (1.f / HW);
    }
}

// ---------------- kv[b,h,d,e] = (1/n) sum_n k_rope[n,d] v[n,e] -----------------
__global__ __launch_bounds__(256) void kv_kernel() {
    int h = blockIdx.x, b = blockIdx.y;
    __shared__ float ks[64][36];
    __shared__ float vs[64][33];
    const float* kp = g_kr + ((size_t)b * CC + h * DD) * HW;
    const float* vp = g_t  + ((size_t)b * CC + h * DD) * HW;
    int t = threadIdx.x;
    int e = t & 31, d0 = (t >> 5) * 4;
    float a0 = 0.f, a1 = 0.f, a2 = 0.f, a3 = 0.f;
    for (int n0 = 0; n0 < HW; n0 += 64) {
#pragma unroll
        for (int l = 0; l < 8; l++) {
            int i  = t + l * 256;
            int dd = i >> 6, nn = i & 63;
            ks[nn][dd] = kp[(size_t)dd * HW + n0 + nn];
            vs[nn][dd] = vp[(size_t)dd * HW + n0 + nn];
        }
        __syncthreads();
#pragma unroll 4
        for (int nn = 0; nn < 64; nn++) {
            float4 kk = *(const float4*)&ks[nn][d0];
            float  vv = vs[nn][e];
            a0 += kk.x * vv; a1 += kk.y * vv; a2 += kk.z * vv; a3 += kk.w * vv;
        }
        __syncthreads();
    }
    float sc = 1.f / HW;
    int base = ((b * HEADS + h) * DD + d0) * DD + e;
    g_kv[base]          = a0 * sc;
    g_kv[base + DD]     = a1 * sc;
    g_kv[base + 2 * DD] = a2 * sc;
    g_kv[base + 3 * DD] = a3 * sc;
}

// ---------------- attn[b,h,n,e] = z * sum_d q_rope[n,d] kv[d,e] ----------------
__global__ __launch_bounds__(256) void attn_kernel() {
    int tile = blockIdx.x, h = blockIdx.y, b = blockIdx.z;
    __shared__ float kvs[DD * DD];
    __shared__ float km[DD];
    int t = threadIdx.x;
#pragma unroll
    for (int l = 0; l < 4; l++)
        kvs[t + l * 256] = g_kv[(b * HEADS + h) * DD * DD + t + l * 256];
    if (t < DD) km[t] = g_km[b * CC + h * DD + t];
    __syncthreads();
    int pix = tile * 256 + t;
    const float* qp  = g_q  + ((size_t)b * CC + h * DD) * HW + pix;
    const float* qrp = g_qr + ((size_t)b * CC + h * DD) * HW + pix;
    float s = 0.f;
#pragma unroll
    for (int d = 0; d < DD; d++) s += qp[(size_t)d * HW] * km[d];
    float z = 1.f / (s + 1e-6f);
    float acc[DD];
#pragma unroll
    for (int e2 = 0; e2 < DD; e2++) acc[e2] = 0.f;
#pragma unroll 8
    for (int d = 0; d < DD; d++) {
        float qd = qrp[(size_t)d * HW];
#pragma unroll
        for (int e2 = 0; e2 < DD; e2++) acc[e2] += qd * kvs[d * DD + e2];
    }
    float* op = g_attn + ((size_t)b * CC + h * DD) * HW + pix;
#pragma unroll
    for (int e2 = 0; e2 < DD; e2++) op[(size_t)e2 * HW] = acc[e2] * z;
}

// ---------------- host ----------------------------------------------------------
extern "C" void kernel_launch(void* const* d_in, const int* in_sizes, int n_in,
                              void* d_out, int out_size)
{
    const float* x      = (const float*)d_in[0];
    const float* cpe1_w = (const float*)d_in[1];
    const float* cpe1_b = (const float*)d_in[2];
    const float* n1_w   = (const float*)d_in[3];
    const float* n1_b   = (const float*)d_in[4];
    const float* ap_w   = (const float*)d_in[5];
    const float* ap_b   = (const float*)d_in[6];
    const float* ip_w   = (const float*)d_in[7];
    const float* ip_b   = (const float*)d_in[8];
    const float* dwc_w  = (const float*)d_in[9];
    const float* dwc_b  = (const float*)d_in[10];
    const float* qkw    = (const float*)d_in[11];
    const float* qkb    = (const float*)d_in[12];
    const float* lepe_w = (const float*)d_in[13];
    const float* lepe_b = (const float*)d_in[14];
    const float* op_w   = (const float*)d_in[15];
    const float* op_b   = (const float*)d_in[16];
    const float* cpe2_w = (const float*)d_in[17];
    const float* cpe2_b = (const float*)d_in[18];
    const float* n2_w   = (const float*)d_in[19];
    const float* n2_b   = (const float*)d_in[20];
    const float* fc1_w  = (const float*)d_in[21];
    const float* fc1_b  = (const float*)d_in[22];
    const float* fc2_w  = (const float*)d_in[23];
    const float* fc2_b  = (const float*)d_in[24];
    float* out = (float*)d_out;

    void* tmp;
    cudaGetSymbolAddress(&tmp, g_x);    float* px    = (float*)tmp;
    cudaGetSymbolAddress(&tmp, g_y);    float* py    = (float*)tmp;
    cudaGetSymbolAddress(&tmp, g_act);  float* pact  = (float*)tmp;
    cudaGetSymbolAddress(&tmp, g_t);    float* pt    = (float*)tmp;
    cudaGetSymbolAddress(&tmp, g_qk);   float* pqk   = (float*)tmp;
    cudaGetSymbolAddress(&tmp, g_attn); float* pattn = (float*)tmp;
    cudaGetSymbolAddress(&tmp, g_h);    float* ph    = (float*)tmp;

    rope_init_kernel<<<(NPAIR * HW + 255) / 256, 256>>>();

    // x = x + cpe1(x)
    dw_kernel<1><<<BB * CC, 256>>>(x, cpe1_w, cpe1_b, x, nullptr, px);

    // y = norm1(x)
    ln_kernel<<<dim3(HW / 256, BB), 256>>>(px, n1_w, n1_b, py);

    // act_res = silu(act_proj(y));  t0 = in_proj(y)
    gemm_tc<1, false><<<dim3(HW / 128, CC / 64, BB), 256>>>(py, ap_w, ap_b, nullptr, pact, CC, CC);
    gemm_tc<0, false><<<dim3(HW / 128, CC / 64, BB), 256>>>(py, ip_w, ip_b, nullptr, pt,   CC, CC);

    // t = silu(dwc(t0))
    dw_kernel<2><<<BB * CC, 256>>>(pt, dwc_w, dwc_b, nullptr, nullptr, pt);

    // qk = qk_w @ t + qk_b
    gemm_tc<0, false><<<dim3(HW / 128, 2 * CC / 64, BB), 256>>>(pt, qkw, qkb, nullptr, pqk, CC, 2 * CC);

    // q/k = elu+1, rope, kmean
    qkpost_kernel<<<dim3(NPAIR, BB), 256>>>();

    // kv, attn
    kv_kernel<<<dim3(HEADS, BB), 256>>>();
    attn_kernel<<<dim3(HW / 256, HEADS, BB), 256>>>();

    // gated = (attn + lepe(v)) * act_res
    dw_kernel<3><<<BB * CC, 256>>>(pt, lepe_w, lepe_b, pattn, pact, pattn);

    // x = x + out_proj(gated)
    gemm_tc<0, true><<<dim3(HW / 128, CC / 64, BB), 256>>>(pattn, op_w, op_b, px, px, CC, CC);

    // x = x + cpe2(x)
    dw_kernel<1><<<BB * CC, 256>>>(px, cpe2_w, cpe2_b, px, nullptr, px);

    // MLP: out = x + fc2(gelu(fc1(norm2(x))))
    ln_kernel<<<dim3(HW / 256, BB), 256>>>(px, n2_w, n2_b, py);
    gemm_tc<2, false><<<dim3(HW / 128, HID / 64, BB), 256>>>(py, fc1_w, fc1_b, nullptr, ph, CC, HID);
    gemm_tc<0, true><<<dim3(HW / 128, CC / 64, BB), 256>>>(ph, fc2_w, fc2_b, px, out, HID, CC);
}

// round 14
// speedup vs baseline: 1.9055x; 1.3446x over previous
#include <cuda_runtime.h>
#include <cuda_bf16.h>
#include <cstdint>
#include <math.h>

#define HW   4096
#define BB   16
#define CC   192
#define HEADS 6
#define DD   32
#define HID  768
#define NPAIR 96

// ---------------- scratch (device globals; no allocation APIs) ----------------
__device__ float g_x   [(size_t)BB*CC*HW];
__device__ float g_y   [(size_t)BB*CC*HW];
__device__ float g_act [(size_t)BB*CC*HW];
__device__ float g_t   [(size_t)BB*CC*HW];
__device__ float g_qk  [(size_t)BB*2*CC*HW];
__device__ float g_q   [(size_t)BB*CC*HW];
__device__ float g_qr  [(size_t)BB*CC*HW];
__device__ float g_kr  [(size_t)BB*CC*HW];
__device__ float g_attn[(size_t)BB*CC*HW];
__device__ float g_h   [(size_t)BB*HID*HW];
__device__ float g_kv  [BB*HEADS*DD*DD];
__device__ float g_km  [BB*CC];
__device__ float g_cos [NPAIR*HW];
__device__ float g_sin [NPAIR*HW];

// ---------------- RoPE tables (double math to match numpy fp64 -> fp32) -------
__global__ void rope_init_kernel() {
    int idx = blockIdx.x * 256 + threadIdx.x;
    if (idx >= NPAIR * HW) return;
    int p   = idx / HW;
    int pix = idx % HW;
    int h = pix >> 6, w = pix & 63;
    int j   = (p < 48) ? p : p - 48;
    int pos = (p < 48) ? h : w;
    double theta = pow(10000.0, -(double)j / 48.0);
    double ang = (double)pos * theta;
    g_cos[idx] = (float)cos(ang);
    g_sin[idx] = (float)sin(ang);
}

// ---------------- depthwise 3x3 ------------------------------------------------
template <int MODE>
__global__ __launch_bounds__(256) void dw_kernel(
    const float* __restrict__ in, const float* __restrict__ wt,
    const float* __restrict__ bs, const float* __restrict__ add,
    const float* __restrict__ gate, float* __restrict__ out)
{
    __shared__ float sp[HW];
    int bc = blockIdx.x;
    int c  = bc % CC;
    const float* ip = in + (size_t)bc * HW;
    int t = threadIdx.x;
#pragma unroll
    for (int i = 0; i < 16; i++) sp[t + i * 256] = ip[t + i * 256];
    float w[9];
#pragma unroll
    for (int i = 0; i < 9; i++) w[i] = wt[c * 9 + i];
    float bb = bs[c];
    __syncthreads();
    for (int i = t; i < HW; i += 256) {
        int y = i >> 6, x = i & 63;
        float s = bb;
#pragma unroll
        for (int ki = 0; ki < 3; ki++) {
            int yy = y + ki - 1;
            if ((unsigned)yy < 64u) {
#pragma unroll
                for (int kj = 0; kj < 3; kj++) {
                    int xx = x + kj - 1;
                    if ((unsigned)xx < 64u) s += w[ki * 3 + kj] * sp[yy * 64 + xx];
                }
            }
        }
        size_t o = (size_t)bc * HW + i;
        if (MODE == 1)      out[o] = add[o] + s;
        else if (MODE == 2) out[o] = s / (1.f + expf(-s));
        else                out[o] = (add[o] + s) * gate[o];
    }
}

// ---------------- LayerNorm over channels (per pixel) --------------------------
__global__ __launch_bounds__(256) void ln_kernel(
    const float* __restrict__ in, const float* __restrict__ w,
    const float* __restrict__ b, float* __restrict__ out)
{
    int bi  = blockIdx.y;
    int pix = blockIdx.x * 256 + threadIdx.x;
    const float* ip = in + (size_t)bi * CC * HW + pix;
    float s = 0.f, s2 = 0.f;
#pragma unroll 4
    for (int c = 0; c < CC; c++) { float v = ip[(size_t)c * HW]; s += v; s2 += v * v; }
    float mu  = s * (1.f / CC);
    float var = s2 * (1.f / CC) - mu * mu;
    float r   = rsqrtf(var + 1e-5f);
    float* op = out + (size_t)bi * CC * HW + pix;
#pragma unroll 4
    for (int c = 0; c < CC; c++)
        op[(size_t)c * HW] = (ip[(size_t)c * HW] - mu) * r * w[c] + b[c];
}

// ---------------- bf16 mma helpers ---------------------------------------------
__device__ __forceinline__ unsigned pack_bf2(float lo, float hi) {
    __nv_bfloat162 h = __floats2bfloat162_rn(lo, hi);   // .x = lo (low 16 bits)
    return *(unsigned*)&h;
}
__device__ __forceinline__ void ldm_x4(unsigned& r0, unsigned& r1, unsigned& r2,
                                       unsigned& r3, unsigned addr) {
    asm volatile("ldmatrix.sync.aligned.m8n8.x4.shared.b16 {%0,%1,%2,%3}, [%4];"
                 : "=r"(r0), "=r"(r1), "=r"(r2), "=r"(r3) : "r"(addr));
}
__device__ __forceinline__ void ldm_x4_t(unsigned& r0, unsigned& r1, unsigned& r2,
                                         unsigned& r3, unsigned addr) {
    asm volatile("ldmatrix.sync.aligned.m8n8.x4.trans.shared.b16 {%0,%1,%2,%3}, [%4];"
                 : "=r"(r0), "=r"(r1), "=r"(r2), "=r"(r3) : "r"(addr));
}
__device__ __forceinline__ void mma_bf16(float* c, const unsigned* a, const unsigned* b) {
    asm volatile(
        "mma.sync.aligned.m16n8k16.row.col.f32.bf16.bf16.f32 "
        "{%0,%1,%2,%3}, {%4,%5,%6,%7}, {%8,%9}, {%0,%1,%2,%3};"
        : "+f"(c[0]), "+f"(c[1]), "+f"(c[2]), "+f"(c[3])
        : "r"(a[0]), "r"(a[1]), "r"(a[2]), "r"(a[3]), "r"(b[0]), "r"(b[1]));
}

// ---------------- conv1x1 GEMM on bf16 tensor cores -----------------------------
// out[b,m,p] = act(sum_c W[m,c] in[b,c,p] + bias[m]) (+res)
// Block tile 64(M) x 128(N) x 32(K); 8 warps 2x4, warp tile 32x32;
// m16n8k16 bf16 mma, ldmatrix (A) / ldmatrix.trans (B), reg-prefetch pipeline.
#define AS_LD 40    // As row stride (bf16): 5 x 16B (odd) -> conflict-free ldmatrix
#define BS_LD 136   // Bs row stride (bf16): 17 x 16B (odd)
template <int ACT, bool RES>
__global__ __launch_bounds__(256) void gemm_tc(
    const float* __restrict__ in, const float* __restrict__ Wm,
    const float* __restrict__ bias, const float* __restrict__ res,
    float* __restrict__ out, int Cin, int Cout)
{
    __shared__ __nv_bfloat16 As[64 * AS_LD];
    __shared__ __nv_bfloat16 Bs[32 * BS_LD];

    const int b  = blockIdx.z;
    const int mb = blockIdx.y * 64, nb = blockIdx.x * 128;
    const int t  = threadIdx.x;
    const int w  = t >> 5, lane = t & 31;
    const int g  = lane >> 2, tq = lane & 3;
    const int wm = (w >> 2) * 32, wn = (w & 3) * 32;

    const float* inb = in + (size_t)b * Cin * HW;
    const int amr = t >> 2, akk = (t & 3) * 8;         // A loader: row, k-span
    const float* wp = Wm + (size_t)(mb + amr) * Cin + akk;
    const int bkr = t >> 3, bnn = (t & 7) * 16;        // B loader: k-row, n-span
    const float* xp = inb + (size_t)bkr * HW + nb + bnn;

    const unsigned asB = (unsigned)__cvta_generic_to_shared(As);
    const unsigned bsB = (unsigned)__cvta_generic_to_shared(Bs);

    // ldmatrix lane addressing components
    const int aRow = (lane & 15);                 // + wm + i*16
    const int aKof = (lane >> 4) << 3;
    const int bKrw = (lane & 7) + (((lane >> 3) & 1) << 3);
    const int bNof = (lane >> 4) << 3;            // + wn + j2*16

    float c[2][4][4];
#pragma unroll
    for (int i = 0; i < 2; i++)
#pragma unroll
        for (int j = 0; j < 4; j++)
#pragma unroll
            for (int q = 0; q < 4; q++) c[i][j][q] = 0.f;

    float4 pa0, pa1, pb0, pb1, pb2, pb3;
    pa0 = *(const float4*)(wp);
    pa1 = *(const float4*)(wp + 4);
    pb0 = *(const float4*)(xp);
    pb1 = *(const float4*)(xp + 4);
    pb2 = *(const float4*)(xp + 8);
    pb3 = *(const float4*)(xp + 12);

    const int nchunk = Cin >> 5;
    for (int ch = 0; ch < nchunk; ch++) {
        // store chunk to smem as bf16
        {
            uint4 va;
            va.x = pack_bf2(pa0.x, pa0.y); va.y = pack_bf2(pa0.z, pa0.w);
            va.z = pack_bf2(pa1.x, pa1.y); va.w = pack_bf2(pa1.z, pa1.w);
            *(uint4*)(&As[amr * AS_LD + akk]) = va;
            uint4 vb;
            vb.x = pack_bf2(pb0.x, pb0.y); vb.y = pack_bf2(pb0.z, pb0.w);
            vb.z = pack_bf2(pb1.x, pb1.y); vb.w = pack_bf2(pb1.z, pb1.w);
            *(uint4*)(&Bs[bkr * BS_LD + bnn]) = vb;
            vb.x = pack_bf2(pb2.x, pb2.y); vb.y = pack_bf2(pb2.z, pb2.w);
            vb.z = pack_bf2(pb3.x, pb3.y); vb.w = pack_bf2(pb3.z, pb3.w);
            *(uint4*)(&Bs[bkr * BS_LD + bnn + 8]) = vb;
        }
        __syncthreads();
        if (ch + 1 < nchunk) {
            int k0 = (ch + 1) << 5;
            pa0 = *(const float4*)(wp + k0);
            pa1 = *(const float4*)(wp + k0 + 4);
            const float* xq = xp + (size_t)k0 * HW;
            pb0 = *(const float4*)(xq);
            pb1 = *(const float4*)(xq + 4);
            pb2 = *(const float4*)(xq + 8);
            pb3 = *(const float4*)(xq + 12);
        }
#pragma unroll
        for (int ks = 0; ks < 2; ks++) {
            const int k0 = ks * 16;
            unsigned a[2][4], bq[2][4];
#pragma unroll
            for (int i = 0; i < 2; i++)
                ldm_x4(a[i][0], a[i][1], a[i][2], a[i][3],
                       asB + (unsigned)(((wm + i * 16 + aRow) * AS_LD + k0 + aKof) * 2));
#pragma unroll
            for (int j2 = 0; j2 < 2; j2++)
                ldm_x4_t(bq[j2][0], bq[j2][1], bq[j2][2], bq[j2][3],
                         bsB + (unsigned)(((k0 + bKrw) * BS_LD + wn + j2 * 16 + bNof) * 2));
#pragma unroll
            for (int i = 0; i < 2; i++)
#pragma unroll
                for (int j = 0; j < 4; j++) {
                    unsigned bb[2] = { bq[j >> 1][(j & 1) * 2], bq[j >> 1][(j & 1) * 2 + 1] };
                    mma_bf16(c[i][j], a[i], bb);
                }
        }
        __syncthreads();
    }

    // epilogue: c0,c1 -> row g cols 2tq,2tq+1 ; c2,c3 -> row g+8
#pragma unroll
    for (int i = 0; i < 2; i++) {
#pragma unroll
        for (int rh = 0; rh < 2; rh++) {
            int m = mb + wm + i * 16 + g + rh * 8;
            float bi = bias[m];
            size_t rowoff = ((size_t)b * Cout + m) * HW + nb;
#pragma unroll
            for (int j = 0; j < 4; j++) {
                int n = wn + j * 8 + tq * 2;
                float v0 = c[i][j][rh * 2 + 0] + bi;
                float v1 = c[i][j][rh * 2 + 1] + bi;
                if (ACT == 1) { v0 = v0 / (1.f + expf(-v0)); v1 = v1 / (1.f + expf(-v1)); }
                if (ACT == 2) {
                    v0 = 0.5f * v0 * (1.f + erff(v0 * 0.70710678118654752f));
                    v1 = 0.5f * v1 * (1.f + erff(v1 * 0.70710678118654752f));
                }
                if (RES) {
                    const float* rp = res + rowoff + n;
                    v0 += rp[0]; v1 += rp[1];
                }
                *(float2*)(out + rowoff + n) = make_float2(v0, v1);
            }
        }
    }
}

// ---------------- elu+1, RoPE(q,k), kmean --------------------------------------
__global__ __launch_bounds__(256) void qkpost_kernel() {
    int b = blockIdx.y, p = blockIdx.x;
    int c0 = 2 * p;
    const float* qp0 = g_qk + ((size_t)b * 2 * CC + c0) * HW;
    const float* qp1 = qp0 + HW;
    const float* kp0 = g_qk + ((size_t)b * 2 * CC + CC + c0) * HW;
    const float* kp1 = kp0 + HW;
    size_t o0 = ((size_t)b * CC + c0) * HW;
    const float* cb = g_cos + (size_t)p * HW;
    const float* sb = g_sin + (size_t)p * HW;
    float sk0 = 0.f, sk1 = 0.f;
    for (int i = threadIdx.x; i < HW; i += 256) {
        float qa = qp0[i]; qa = (qa > 0.f) ? qa + 1.f : expf(qa);
        float qb = qp1[i]; qb = (qb > 0.f) ? qb + 1.f : expf(qb);
        float ka = kp0[i]; ka = (ka > 0.f) ? ka + 1.f : expf(ka);
        float kb = kp1[i]; kb = (kb > 0.f) ? kb + 1.f : expf(kb);
        float cs = cb[i], sn = sb[i];
        g_q[o0 + i]       = qa;
        g_q[o0 + HW + i]  = qb;
        g_qr[o0 + i]      = qa * cs - qb * sn;
        g_qr[o0 + HW + i] = qa * sn + qb * cs;
        g_kr[o0 + i]      = ka * cs - kb * sn;
        g_kr[o0 + HW + i] = ka * sn + kb * cs;
        sk0 += ka; sk1 += kb;
    }
    __shared__ float r0[256], r1[256];
    int t = threadIdx.x;
    r0[t] = sk0; r1[t] = sk1;
    __syncthreads();
    for (int s = 128; s > 0; s >>= 1) {
        if (t < s) { r0[t] += r0[t + s]; r1[t] += r1[t + s]; }
        __syncthreads();
    }
    if (t == 0) {
        g_km[b * CC + c0]     = r0[0] * (1.f / HW);
        g_km[b * CC + c0 + 1] = r1[0] * (1.f / HW);
    }
}

// ---------------- kv[b,h,d,e] = (1/n) sum_n k_rope[n,d] v[n,e] -----------------
__global__ __launch_bounds__(256) void kv_kernel() {
    int h = blockIdx.x, b = blockIdx.y;
    __shared__ float ks[64][36];
    __shared__ float vs[64][33];
    const float* kp = g_kr + ((size_t)b * CC + h * DD) * HW;
    const float* vp = g_t  + ((size_t)b * CC + h * DD) * HW;
    int t = threadIdx.x;
    int e = t & 31, d0 = (t >> 5) * 4;
    float a0 = 0.f, a1 = 0.f, a2 = 0.f, a3 = 0.f;
    for (int n0 = 0; n0 < HW; n0 += 64) {
#pragma unroll
        for (int l = 0; l < 8; l++) {
            int i  = t + l * 256;
            int dd = i >> 6, nn = i & 63;
            ks[nn][dd] = kp[(size_t)dd * HW + n0 + nn];
            vs[nn][dd] = vp[(size_t)dd * HW + n0 + nn];
        }
        __syncthreads();
#pragma unroll 4
        for (int nn = 0; nn < 64; nn++) {
            float4 kk = *(const float4*)&ks[nn][d0];
            float  vv = vs[nn][e];
            a0 += kk.x * vv; a1 += kk.y * vv; a2 += kk.z * vv; a3 += kk.w * vv;
        }
        __syncthreads();
    }
    float sc = 1.f / HW;
    int base = ((b * HEADS + h) * DD + d0) * DD + e;
    g_kv[base]          = a0 * sc;
    g_kv[base + DD]     = a1 * sc;
    g_kv[base + 2 * DD] = a2 * sc;
    g_kv[base + 3 * DD] = a3 * sc;
}

// ---------------- attn[b,h,n,e] = z * sum_d q_rope[n,d] kv[d,e] ----------------
__global__ __launch_bounds__(256) void attn_kernel() {
    int tile = blockIdx.x, h = blockIdx.y, b = blockIdx.z;
    __shared__ float kvs[DD * DD];
    __shared__ float km[DD];
    int t = threadIdx.x;
#pragma unroll
    for (int l = 0; l < 4; l++)
        kvs[t + l * 256] = g_kv[(b * HEADS + h) * DD * DD + t + l * 256];
    if (t < DD) km[t] = g_km[b * CC + h * DD + t];
    __syncthreads();
    int pix = tile * 256 + t;
    const float* qp  = g_q  + ((size_t)b * CC + h * DD) * HW + pix;
    const float* qrp = g_qr + ((size_t)b * CC + h * DD) * HW + pix;
    float s = 0.f;
#pragma unroll
    for (int d = 0; d < DD; d++) s += qp[(size_t)d * HW] * km[d];
    float z = 1.f / (s + 1e-6f);
    float acc[DD];
#pragma unroll
    for (int e2 = 0; e2 < DD; e2++) acc[e2] = 0.f;
#pragma unroll 8
    for (int d = 0; d < DD; d++) {
        float qd = qrp[(size_t)d * HW];
#pragma unroll
        for (int e2 = 0; e2 < DD; e2++) acc[e2] += qd * kvs[d * DD + e2];
    }
    float* op = g_attn + ((size_t)b * CC + h * DD) * HW + pix;
#pragma unroll
    for (int e2 = 0; e2 < DD; e2++) op[(size_t)e2 * HW] = acc[e2] * z;
}

// ---------------- host ----------------------------------------------------------
extern "C" void kernel_launch(void* const* d_in, const int* in_sizes, int n_in,
                              void* d_out, int out_size)
{
    const float* x      = (const float*)d_in[0];
    const float* cpe1_w = (const float*)d_in[1];
    const float* cpe1_b = (const float*)d_in[2];
    const float* n1_w   = (const float*)d_in[3];
    const float* n1_b   = (const float*)d_in[4];
    const float* ap_w   = (const float*)d_in[5];
    const float* ap_b   = (const float*)d_in[6];
    const float* ip_w   = (const float*)d_in[7];
    const float* ip_b   = (const float*)d_in[8];
    const float* dwc_w  = (const float*)d_in[9];
    const float* dwc_b  = (const float*)d_in[10];
    const float* qkw    = (const float*)d_in[11];
    const float* qkb    = (const float*)d_in[12];
    const float* lepe_w = (const float*)d_in[13];
    const float* lepe_b = (const float*)d_in[14];
    const float* op_w   = (const float*)d_in[15];
    const float* op_b   = (const float*)d_in[16];
    const float* cpe2_w = (const float*)d_in[17];
    const float* cpe2_b = (const float*)d_in[18];
    const float* n2_w   = (const float*)d_in[19];
    const float* n2_b   = (const float*)d_in[20];
    const float* fc1_w  = (const float*)d_in[21];
    const float* fc1_b  = (const float*)d_in[22];
    const float* fc2_w  = (const float*)d_in[23];
    const float* fc2_b  = (const float*)d_in[24];
    float* out = (float*)d_out;

    void* tmp;
    cudaGetSymbolAddress(&tmp, g_x);    float* px    = (float*)tmp;
    cudaGetSymbolAddress(&tmp, g_y);    float* py    = (float*)tmp;
    cudaGetSymbolAddress(&tmp, g_act);  float* pact  = (float*)tmp;
    cudaGetSymbolAddress(&tmp, g_t);    float* pt    = (float*)tmp;
    cudaGetSymbolAddress(&tmp, g_qk);   float* pqk   = (float*)tmp;
    cudaGetSymbolAddress(&tmp, g_attn); float* pattn = (float*)tmp;
    cudaGetSymbolAddress(&tmp, g_h);    float* ph    = (float*)tmp;

    rope_init_kernel<<<(NPAIR * HW + 255) / 256, 256>>>();

    // x = x + cpe1(x)
    dw_kernel<1><<<BB * CC, 256>>>(x, cpe1_w, cpe1_b, x, nullptr, px);

    // y = norm1(x)
    ln_kernel<<<dim3(HW / 256, BB), 256>>>(px, n1_w, n1_b, py);

    // act_res = silu(act_proj(y));  t0 = in_proj(y)
    gemm_tc<1, false><<<dim3(HW / 128, CC / 64, BB), 256>>>(py, ap_w, ap_b, nullptr, pact, CC, CC);
    gemm_tc<0, false><<<dim3(HW / 128, CC / 64, BB), 256>>>(py, ip_w, ip_b, nullptr, pt,   CC, CC);

    // t = silu(dwc(t0))
    dw_kernel<2><<<BB * CC, 256>>>(pt, dwc_w, dwc_b, nullptr, nullptr, pt);

    // qk = qk_w @ t + qk_b
    gemm_tc<0, false><<<dim3(HW / 128, 2 * CC / 64, BB), 256>>>(pt, qkw, qkb, nullptr, pqk, CC, 2 * CC);

    // q/k = elu+1, rope, kmean
    qkpost_kernel<<<dim3(NPAIR, BB), 256>>>();

    // kv, attn
    kv_kernel<<<dim3(HEADS, BB), 256>>>();
    attn_kernel<<<dim3(HW / 256, HEADS, BB), 256>>>();

    // gated = (attn + lepe(v)) * act_res
    dw_kernel<3><<<BB * CC, 256>>>(pt, lepe_w, lepe_b, pattn, pact, pattn);

    // x = x + out_proj(gated)
    gemm_tc<0, true><<<dim3(HW / 128, CC / 64, BB), 256>>>(pattn, op_w, op_b, px, px, CC, CC);

    // x = x + cpe2(x)
    dw_kernel<1><<<BB * CC, 256>>>(px, cpe2_w, cpe2_b, px, nullptr, px);

    // MLP: out = x + fc2(gelu(fc1(norm2(x))))
    ln_kernel<<<dim3(HW / 256, BB), 256>>>(px, n2_w, n2_b, py);
    gemm_tc<2, false><<<dim3(HW / 128, HID / 64, BB), 256>>>(py, fc1_w, fc1_b, nullptr, ph, CC, HID);
    gemm_tc<0, true><<<dim3(HW / 128, CC / 64, BB), 256>>>(ph, fc2_w, fc2_b, px, out, HID, CC);
}

// round 15
// speedup vs baseline: 2.4987x; 1.3113x over previous
#include <cuda_runtime.h>
#include <cuda_bf16.h>
#include <cstdint>
#include <math.h>

#define HW   4096
#define BB   16
#define CC   192
#define HEADS 6
#define DD   32
#define HID  768
#define NPAIR 96

// ---------------- scratch (device globals; no allocation APIs) ----------------
__device__ float g_x   [(size_t)BB*CC*HW];
__device__ float g_y   [(size_t)BB*CC*HW];
__device__ float g_act [(size_t)BB*CC*HW];
__device__ float g_t   [(size_t)BB*CC*HW];
__device__ float g_qk  [(size_t)BB*2*CC*HW];
__device__ float g_q   [(size_t)BB*CC*HW];
__device__ float g_qr  [(size_t)BB*CC*HW];   // also reused as bf16 't' for qk GEMM
__device__ float g_kr  [(size_t)BB*CC*HW];
__device__ float g_attn[(size_t)BB*CC*HW];
__device__ float g_h   [(size_t)BB*HID*HW];  // bf16 gated buffer, then bf16 fc1 out
__device__ float g_kv  [BB*HEADS*DD*DD];
__device__ float g_km  [BB*CC];
__device__ float g_cos [NPAIR*HW];
__device__ float g_sin [NPAIR*HW];
__device__ __nv_bfloat16 g_wb[480256];       // bf16 weight scratch

// weight offsets in g_wb
#define WB_AP  0
#define WB_IP  36864
#define WB_QK  73728
#define WB_OP  147456
#define WB_FC1 184320
#define WB_FC2 331776

// ---------------- fp32 -> bf16 convert ------------------------------------------
__global__ void cvt_kernel(const float* __restrict__ s, __nv_bfloat16* __restrict__ d, int n) {
    int i = blockIdx.x * 256 + threadIdx.x;
    if (i < n) d[i] = __float2bfloat16(s[i]);
}

// ---------------- RoPE tables (double math to match numpy fp64 -> fp32) -------
__global__ void rope_init_kernel() {
    int idx = blockIdx.x * 256 + threadIdx.x;
    if (idx >= NPAIR * HW) return;
    int p   = idx / HW;
    int pix = idx % HW;
    int h = pix >> 6, w = pix & 63;
    int j   = (p < 48) ? p : p - 48;
    int pos = (p < 48) ? h : w;
    double theta = pow(10000.0, -(double)j / 48.0);
    double ang = (double)pos * theta;
    g_cos[idx] = (float)cos(ang);
    g_sin[idx] = (float)sin(ang);
}

// ---------------- depthwise 3x3 ------------------------------------------------
// MODE 1: out = add + dw(in)                      (fp32)
// MODE 2: out = silu(dw(in)) fp32 + bf16 copy
// MODE 3: outb = bf16((add + dw(in)) * gate)
template <int MODE>
__global__ __launch_bounds__(256) void dw_kernel(
    const float* __restrict__ in, const float* __restrict__ wt,
    const float* __restrict__ bs, const float* __restrict__ add,
    const float* __restrict__ gate, float* __restrict__ out,
    __nv_bfloat16* __restrict__ outb)
{
    __shared__ float sp[HW];
    int bc = blockIdx.x;
    int c  = bc % CC;
    const float* ip = in + (size_t)bc * HW;
    int t = threadIdx.x;
#pragma unroll
    for (int i = 0; i < 16; i++) sp[t + i * 256] = ip[t + i * 256];
    float w[9];
#pragma unroll
    for (int i = 0; i < 9; i++) w[i] = wt[c * 9 + i];
    float bb = bs[c];
    __syncthreads();
    for (int i = t; i < HW; i += 256) {
        int y = i >> 6, x = i & 63;
        float s = bb;
#pragma unroll
        for (int ki = 0; ki < 3; ki++) {
            int yy = y + ki - 1;
            if ((unsigned)yy < 64u) {
#pragma unroll
                for (int kj = 0; kj < 3; kj++) {
                    int xx = x + kj - 1;
                    if ((unsigned)xx < 64u) s += w[ki * 3 + kj] * sp[yy * 64 + xx];
                }
            }
        }
        size_t o = (size_t)bc * HW + i;
        if (MODE == 1) {
            out[o] = add[o] + s;
        } else if (MODE == 2) {
            float v = s / (1.f + expf(-s));
            out[o]  = v;
            outb[o] = __float2bfloat16(v);
        } else {
            outb[o] = __float2bfloat16((add[o] + s) * gate[o]);
        }
    }
}

// ---------------- LayerNorm over channels (per pixel), bf16 output -------------
__global__ __launch_bounds__(256) void ln_kernel(
    const float* __restrict__ in, const float* __restrict__ w,
    const float* __restrict__ b, __nv_bfloat16* __restrict__ out)
{
    int bi  = blockIdx.y;
    int pix = blockIdx.x * 256 + threadIdx.x;
    const float* ip = in + (size_t)bi * CC * HW + pix;
    float s = 0.f, s2 = 0.f;
#pragma unroll 4
    for (int c = 0; c < CC; c++) { float v = ip[(size_t)c * HW]; s += v; s2 += v * v; }
    float mu  = s * (1.f / CC);
    float var = s2 * (1.f / CC) - mu * mu;
    float r   = rsqrtf(var + 1e-5f);
    __nv_bfloat16* op = out + (size_t)bi * CC * HW + pix;
#pragma unroll 4
    for (int c = 0; c < CC; c++)
        op[(size_t)c * HW] = __float2bfloat16((ip[(size_t)c * HW] - mu) * r * w[c] + b[c]);
}

// ---------------- mma / ldmatrix / cp.async helpers ------------------------------
__device__ __forceinline__ unsigned pack_bf2(float lo, float hi) {
    __nv_bfloat162 h = __floats2bfloat162_rn(lo, hi);
    return *(unsigned*)&h;
}
__device__ __forceinline__ void ldm_x4(unsigned& r0, unsigned& r1, unsigned& r2,
                                       unsigned& r3, unsigned addr) {
    asm volatile("ldmatrix.sync.aligned.m8n8.x4.shared.b16 {%0,%1,%2,%3}, [%4];"
                 : "=r"(r0), "=r"(r1), "=r"(r2), "=r"(r3) : "r"(addr));
}
__device__ __forceinline__ void ldm_x4_t(unsigned& r0, unsigned& r1, unsigned& r2,
                                         unsigned& r3, unsigned addr) {
    asm volatile("ldmatrix.sync.aligned.m8n8.x4.trans.shared.b16 {%0,%1,%2,%3}, [%4];"
                 : "=r"(r0), "=r"(r1), "=r"(r2), "=r"(r3) : "r"(addr));
}
__device__ __forceinline__ void mma_bf16(float* c, const unsigned* a, const unsigned* b) {
    asm volatile(
        "mma.sync.aligned.m16n8k16.row.col.f32.bf16.bf16.f32 "
        "{%0,%1,%2,%3}, {%4,%5,%6,%7}, {%8,%9}, {%0,%1,%2,%3};"
        : "+f"(c[0]), "+f"(c[1]), "+f"(c[2]), "+f"(c[3])
        : "r"(a[0]), "r"(a[1]), "r"(a[2]), "r"(a[3]), "r"(b[0]), "r"(b[1]));
}
__device__ __forceinline__ void cpa16(unsigned smem, const void* g) {
    asm volatile("cp.async.cg.shared.global [%0], [%1], 16;" :: "r"(smem), "l"(g));
}
__device__ __forceinline__ void cpa_commit() { asm volatile("cp.async.commit_group;"); }

// ---------------- conv1x1 GEMM, bf16 in, cp.async 3-stage pipeline ---------------
// out[b,m,p] = act(sum_c W[m,c] in[b,c,p] + bias[m]) (+res)
// Block 64(M) x 128(N) x 32(K); 8 warps 2x4, warp tile 32x32; m16n8k16 bf16.
#define AS_LD 56    // A row stride (bf16) = 112B = 7x16B -> aligned + conflict-free
#define BS_LD 136   // B row stride (bf16) = 272B = 17x16B
#define A_ST (64 * AS_LD)
#define B_ST (32 * BS_LD)
#define NST 3
template <int ACT, bool RES, bool OUTBF>
__global__ __launch_bounds__(256) void gemm_tc(
    const __nv_bfloat16* __restrict__ in, const __nv_bfloat16* __restrict__ Wm,
    const float* __restrict__ bias, const float* __restrict__ res,
    void* __restrict__ outp, int Cin, int Cout)
{
    __shared__ __nv_bfloat16 As[NST * A_ST];
    __shared__ __nv_bfloat16 Bs[NST * B_ST];

    const int b  = blockIdx.z;
    const int mb = blockIdx.y * 64, nb = blockIdx.x * 128;
    const int t  = threadIdx.x;
    const int w  = t >> 5, lane = t & 31;
    const int g  = lane >> 2, tq = lane & 3;
    const int wm = (w >> 2) * 32, wn = (w & 3) * 32;

    const unsigned asB = (unsigned)__cvta_generic_to_shared(As);
    const unsigned bsB = (unsigned)__cvta_generic_to_shared(Bs);

    // loader mapping
    const int amr = t >> 2, akk = (t & 3) * 8;     // A: 64 rows x 4 chunks(16B)
    const __nv_bfloat16* wp = Wm + (size_t)(mb + amr) * Cin + akk;
    const unsigned aDst = asB + (unsigned)((amr * AS_LD + akk) * 2);
    const int bkr = t >> 3, bnn = (t & 7) * 16;    // B: 32 rows x 8 thr x 2 chunks
    const __nv_bfloat16* xp = in + (size_t)b * Cin * HW + (size_t)bkr * HW + nb + bnn;
    const unsigned bDst = bsB + (unsigned)((bkr * BS_LD + bnn) * 2);

    const int nchunk = Cin >> 5;

    auto issue = [&](int ch, int st) {
        cpa16(aDst + (unsigned)(st * A_ST * 2), wp + ch * 32);
        const __nv_bfloat16* xs = xp + (size_t)(ch * 32) * HW;
        cpa16(bDst + (unsigned)(st * B_ST * 2), xs);
        cpa16(bDst + (unsigned)(st * B_ST * 2) + 16, xs + 8);
        cpa_commit();
    };

    // ldmatrix lane addressing
    const int aRow = (lane & 15);
    const int aKof = (lane >> 4) << 3;
    const int bKrw = (lane & 7) + (((lane >> 3) & 1) << 3);
    const int bNof = (lane >> 4) << 3;

    float c[2][4][4];
#pragma unroll
    for (int i = 0; i < 2; i++)
#pragma unroll
        for (int j = 0; j < 4; j++)
#pragma unroll
            for (int q = 0; q < 4; q++) c[i][j][q] = 0.f;

    // prologue: stages 0,1
    issue(0, 0);
    issue(1, 1);

    for (int ch = 0; ch < nchunk; ch++) {
        if (ch + NST - 1 < nchunk) {
            asm volatile("cp.async.wait_group 1;");
        } else {
            asm volatile("cp.async.wait_group 0;");
        }
        __syncthreads();
        if (ch + NST - 1 < nchunk) issue(ch + NST - 1, (ch + NST - 1) % NST);

        const int st = ch % NST;
        const unsigned asS = asB + (unsigned)(st * A_ST * 2);
        const unsigned bsS = bsB + (unsigned)(st * B_ST * 2);
#pragma unroll
        for (int ks = 0; ks < 2; ks++) {
            const int k0 = ks * 16;
            unsigned a[2][4], bq[2][4];
#pragma unroll
            for (int i = 0; i < 2; i++)
                ldm_x4(a[i][0], a[i][1], a[i][2], a[i][3],
                       asS + (unsigned)(((wm + i * 16 + aRow) * AS_LD + k0 + aKof) * 2));
#pragma unroll
            for (int j2 = 0; j2 < 2; j2++)
                ldm_x4_t(bq[j2][0], bq[j2][1], bq[j2][2], bq[j2][3],
                         bsS + (unsigned)(((k0 + bKrw) * BS_LD + wn + j2 * 16 + bNof) * 2));
#pragma unroll
            for (int i = 0; i < 2; i++)
#pragma unroll
                for (int j = 0; j < 4; j++) {
                    unsigned bb[2] = { bq[j >> 1][(j & 1) * 2], bq[j >> 1][(j & 1) * 2 + 1] };
                    mma_bf16(c[i][j], a[i], bb);
                }
        }
        __syncthreads();
    }

    // epilogue
#pragma unroll
    for (int i = 0; i < 2; i++) {
#pragma unroll
        for (int rh = 0; rh < 2; rh++) {
            int m = mb + wm + i * 16 + g + rh * 8;
            float bi = bias[m];
            size_t rowoff = ((size_t)b * Cout + m) * HW + nb;
#pragma unroll
            for (int j = 0; j < 4; j++) {
                int n = wn + j * 8 + tq * 2;
                float v0 = c[i][j][rh * 2 + 0] + bi;
                float v1 = c[i][j][rh * 2 + 1] + bi;
                if (ACT == 1) { v0 = v0 / (1.f + expf(-v0)); v1 = v1 / (1.f + expf(-v1)); }
                if (ACT == 2) {
                    v0 = 0.5f * v0 * (1.f + erff(v0 * 0.70710678118654752f));
                    v1 = 0.5f * v1 * (1.f + erff(v1 * 0.70710678118654752f));
                }
                if (RES) {
                    const float* rp = res + rowoff + n;
                    v0 += rp[0]; v1 += rp[1];
                }
                if (OUTBF) {
                    unsigned pv = pack_bf2(v0, v1);
                    *(unsigned*)((__nv_bfloat16*)outp + rowoff + n) = pv;
                } else {
                    *(float2*)((float*)outp + rowoff + n) = make_float2(v0, v1);
                }
            }
        }
    }
}

// ---------------- elu+1, RoPE(q,k), kmean --------------------------------------
__global__ __launch_bounds__(256) void qkpost_kernel() {
    int b = blockIdx.y, p = blockIdx.x;
    int c0 = 2 * p;
    const float* qp0 = g_qk + ((size_t)b * 2 * CC + c0) * HW;
    const float* qp1 = qp0 + HW;
    const float* kp0 = g_qk + ((size_t)b * 2 * CC + CC + c0) * HW;
    const float* kp1 = kp0 + HW;
    size_t o0 = ((size_t)b * CC + c0) * HW;
    const float* cb = g_cos + (size_t)p * HW;
    const float* sb = g_sin + (size_t)p * HW;
    float sk0 = 0.f, sk1 = 0.f;
    for (int i = threadIdx.x; i < HW; i += 256) {
        float qa = qp0[i]; qa = (qa > 0.f) ? qa + 1.f : expf(qa);
        float qb = qp1[i]; qb = (qb > 0.f) ? qb + 1.f : expf(qb);
        float ka = kp0[i]; ka = (ka > 0.f) ? ka + 1.f : expf(ka);
        float kb = kp1[i]; kb = (kb > 0.f) ? kb + 1.f : expf(kb);
        float cs = cb[i], sn = sb[i];
        g_q[o0 + i]       = qa;
        g_q[o0 + HW + i]  = qb;
        g_qr[o0 + i]      = qa * cs - qb * sn;
        g_qr[o0 + HW + i] = qa * sn + qb * cs;
        g_kr[o0 + i]      = ka * cs - kb * sn;
        g_kr[o0 + HW + i] = ka * sn + kb * cs;
        sk0 += ka; sk1 += kb;
    }
    __shared__ float r0[256], r1[256];
    int t = threadIdx.x;
    r0[t] = sk0; r1[t] = sk1;
    __syncthreads();
    for (int s = 128; s > 0; s >>= 1) {
        if (t < s) { r0[t] += r0[t + s]; r1[t] += r1[t + s]; }
        __syncthreads();
    }
    if (t == 0) {
        g_km[b * CC + c0]     = r0[0] * (1.f / HW);
        g_km[b * CC + c0 + 1] = r1[0] * (1.f / HW);
    }
}

// ---------------- kv[b,h,d,e] = (1/n) sum_n k_rope[n,d] v[n,e] -----------------
__global__ __launch_bounds__(256) void kv_kernel() {
    int h = blockIdx.x, b = blockIdx.y;
    __shared__ float ks[64][36];
    __shared__ float vs[64][33];
    const float* kp = g_kr + ((size_t)b * CC + h * DD) * HW;
    const float* vp = g_t  + ((size_t)b * CC + h * DD) * HW;
    int t = threadIdx.x;
    int e = t & 31, d0 = (t >> 5) * 4;
    float a0 = 0.f, a1 = 0.f, a2 = 0.f, a3 = 0.f;
    for (int n0 = 0; n0 < HW; n0 += 64) {
#pragma unroll
        for (int l = 0; l < 8; l++) {
            int i  = t + l * 256;
            int dd = i >> 6, nn = i & 63;
            ks[nn][dd] = kp[(size_t)dd * HW + n0 + nn];
            vs[nn][dd] = vp[(size_t)dd * HW + n0 + nn];
        }
        __syncthreads();
#pragma unroll 4
        for (int nn = 0; nn < 64; nn++) {
            float4 kk = *(const float4*)&ks[nn][d0];
            float  vv = vs[nn][e];
            a0 += kk.x * vv; a1 += kk.y * vv; a2 += kk.z * vv; a3 += kk.w * vv;
        }
        __syncthreads();
    }
    float sc = 1.f / HW;
    int base = ((b * HEADS + h) * DD + d0) * DD + e;
    g_kv[base]          = a0 * sc;
    g_kv[base + DD]     = a1 * sc;
    g_kv[base + 2 * DD] = a2 * sc;
    g_kv[base + 3 * DD] = a3 * sc;
}

// ---------------- attn[b,h,n,e] = z * sum_d q_rope[n,d] kv[d,e] ----------------
__global__ __launch_bounds__(256) void attn_kernel() {
    int tile = blockIdx.x, h = blockIdx.y, b = blockIdx.z;
    __shared__ float kvs[DD * DD];
    __shared__ float km[DD];
    int t = threadIdx.x;
#pragma unroll
    for (int l = 0; l < 4; l++)
        kvs[t + l * 256] = g_kv[(b * HEADS + h) * DD * DD + t + l * 256];
    if (t < DD) km[t] = g_km[b * CC + h * DD + t];
    __syncthreads();
    int pix = tile * 256 + t;
    const float* qp  = g_q  + ((size_t)b * CC + h * DD) * HW + pix;
    const float* qrp = g_qr + ((size_t)b * CC + h * DD) * HW + pix;
    float s = 0.f;
#pragma unroll
    for (int d = 0; d < DD; d++) s += qp[(size_t)d * HW] * km[d];
    float z = 1.f / (s + 1e-6f);
    float acc[DD];
#pragma unroll
    for (int e2 = 0; e2 < DD; e2++) acc[e2] = 0.f;
#pragma unroll 8
    for (int d = 0; d < DD; d++) {
        float qd = qrp[(size_t)d * HW];
#pragma unroll
        for (int e2 = 0; e2 < DD; e2++) acc[e2] += qd * kvs[d * DD + e2];
    }
    float* op = g_attn + ((size_t)b * CC + h * DD) * HW + pix;
#pragma unroll
    for (int e2 = 0; e2 < DD; e2++) op[(size_t)e2 * HW] = acc[e2] * z;
}

// ---------------- host ----------------------------------------------------------
extern "C" void kernel_launch(void* const* d_in, const int* in_sizes, int n_in,
                              void* d_out, int out_size)
{
    const float* x      = (const float*)d_in[0];
    const float* cpe1_w = (const float*)d_in[1];
    const float* cpe1_b = (const float*)d_in[2];
    const float* n1_w   = (const float*)d_in[3];
    const float* n1_b   = (const float*)d_in[4];
    const float* ap_w   = (const float*)d_in[5];
    const float* ap_b   = (const float*)d_in[6];
    const float* ip_w   = (const float*)d_in[7];
    const float* ip_b   = (const float*)d_in[8];
    const float* dwc_w  = (const float*)d_in[9];
    const float* dwc_b  = (const float*)d_in[10];
    const float* qkw    = (const float*)d_in[11];
    const float* qkb    = (const float*)d_in[12];
    const float* lepe_w = (const float*)d_in[13];
    const float* lepe_b = (const float*)d_in[14];
    const float* op_w   = (const float*)d_in[15];
    const float* op_b   = (const float*)d_in[16];
    const float* cpe2_w = (const float*)d_in[17];
    const float* cpe2_b = (const float*)d_in[18];
    const float* n2_w   = (const float*)d_in[19];
    const float* n2_b   = (const float*)d_in[20];
    const float* fc1_w  = (const float*)d_in[21];
    const float* fc1_b  = (const float*)d_in[22];
    const float* fc2_w  = (const float*)d_in[23];
    const float* fc2_b  = (const float*)d_in[24];
    float* out = (float*)d_out;

    void* tmp;
    cudaGetSymbolAddress(&tmp, g_x);    float* px    = (float*)tmp;
    cudaGetSymbolAddress(&tmp, g_y);    __nv_bfloat16* pyb = (__nv_bfloat16*)tmp;
    cudaGetSymbolAddress(&tmp, g_act);  float* pact  = (float*)tmp;
    cudaGetSymbolAddress(&tmp, g_t);    float* pt    = (float*)tmp;
    cudaGetSymbolAddress(&tmp, g_qk);   float* pqk   = (float*)tmp;
    cudaGetSymbolAddress(&tmp, g_qr);   __nv_bfloat16* ptb = (__nv_bfloat16*)tmp;
    cudaGetSymbolAddress(&tmp, g_attn); float* pattn = (float*)tmp;
    cudaGetSymbolAddress(&tmp, g_h);    __nv_bfloat16* phb = (__nv_bfloat16*)tmp;
    cudaGetSymbolAddress(&tmp, g_wb);   __nv_bfloat16* pwb = (__nv_bfloat16*)tmp;

    // weights -> bf16 (once per replay; cheap)
    cvt_kernel<<<(36864 + 255) / 256, 256>>>(ap_w,  pwb + WB_AP,  36864);
    cvt_kernel<<<(36864 + 255) / 256, 256>>>(ip_w,  pwb + WB_IP,  36864);
    cvt_kernel<<<(73728 + 255) / 256, 256>>>(qkw,   pwb + WB_QK,  73728);
    cvt_kernel<<<(36864 + 255) / 256, 256>>>(op_w,  pwb + WB_OP,  36864);
    cvt_kernel<<<(147456 + 255) / 256, 256>>>(fc1_w, pwb + WB_FC1, 147456);
    cvt_kernel<<<(147456 + 255) / 256, 256>>>(fc2_w, pwb + WB_FC2, 147456);

    rope_init_kernel<<<(NPAIR * HW + 255) / 256, 256>>>();

    // x = x + cpe1(x)
    dw_kernel<1><<<BB * CC, 256>>>(x, cpe1_w, cpe1_b, x, nullptr, px, nullptr);

    // y = norm1(x)  (bf16)
    ln_kernel<<<dim3(HW / 256, BB), 256>>>(px, n1_w, n1_b, pyb);

    // act_res = silu(act_proj(y));  t0 = in_proj(y)
    gemm_tc<1, false, false><<<dim3(HW / 128, CC / 64, BB), 256>>>(pyb, pwb + WB_AP, ap_b, nullptr, pact, CC, CC);
    gemm_tc<0, false, false><<<dim3(HW / 128, CC / 64, BB), 256>>>(pyb, pwb + WB_IP, ip_b, nullptr, pt,   CC, CC);

    // t = silu(dwc(t0))  -> fp32 pt + bf16 ptb
    dw_kernel<2><<<BB * CC, 256>>>(pt, dwc_w, dwc_b, nullptr, nullptr, pt, ptb);

    // qk = qk_w @ t + qk_b
    gemm_tc<0, false, false><<<dim3(HW / 128, 2 * CC / 64, BB), 256>>>(ptb, pwb + WB_QK, qkb, nullptr, pqk, CC, 2 * CC);

    // q/k = elu+1, rope, kmean   (overwrites g_qr with fp32 q_rope)
    qkpost_kernel<<<dim3(NPAIR, BB), 256>>>();

    // kv, attn
    kv_kernel<<<dim3(HEADS, BB), 256>>>();
    attn_kernel<<<dim3(HW / 256, HEADS, BB), 256>>>();

    // gated = bf16((attn + lepe(v)) * act_res)
    dw_kernel<3><<<BB * CC, 256>>>(pt, lepe_w, lepe_b, pattn, pact, nullptr, phb);

    // x = x + out_proj(gated)
    gemm_tc<0, true, false><<<dim3(HW / 128, CC / 64, BB), 256>>>(phb, pwb + WB_OP, op_b, px, px, CC, CC);

    // x = x + cpe2(x)
    dw_kernel<1><<<BB * CC, 256>>>(px, cpe2_w, cpe2_b, px, nullptr, px, nullptr);

    // MLP: out = x + fc2(gelu(fc1(norm2(x))))
    ln_kernel<<<dim3(HW / 256, BB), 256>>>(px, n2_w, n2_b, pyb);
    gemm_tc<2, false, true><<<dim3(HW / 128, HID / 64, BB), 256>>>(pyb, pwb + WB_FC1, fc1_b, nullptr, phb, CC, HID);
    gemm_tc<0, true, false><<<dim3(HW / 128, CC / 64, BB), 256>>>(phb, pwb + WB_FC2, fc2_b, px, out, HID, CC);
}

// round 16
// speedup vs baseline: 2.6590x; 1.0642x over previous
#include <cuda_runtime.h>
#include <cuda_bf16.h>
#include <cstdint>
#include <math.h>

#define HW   4096
#define BB   16
#define CC   192
#define HEADS 6
#define DD   32
#define HID  768
#define NPAIR 96

// ---------------- scratch (device globals; no allocation APIs) ----------------
__device__ float g_x   [(size_t)BB*CC*HW];
__device__ float g_y   [(size_t)BB*CC*HW];
__device__ float g_act [(size_t)BB*CC*HW];
__device__ float g_t   [(size_t)BB*CC*HW];
__device__ float g_qk  [(size_t)BB*2*CC*HW];
__device__ float g_qr  [(size_t)BB*CC*HW];   // bf16 't' alias before qkpost
__device__ float g_kr  [(size_t)BB*CC*HW];
__device__ float g_attn[(size_t)BB*CC*HW];
__device__ float g_h   [(size_t)BB*HID*HW];  // bf16 gated buffer, then bf16 fc1 out
__device__ float g_kv  [BB*HEADS*DD*DD];
__device__ float g_km  [BB*CC];
__device__ float g_cos [NPAIR*HW];
__device__ float g_sin [NPAIR*HW];
__device__ __nv_bfloat16 g_wb[480256];       // bf16 weight scratch

// weight offsets in g_wb
#define WB_AP  0
#define WB_IP  36864
#define WB_QK  73728
#define WB_OP  147456
#define WB_FC1 184320
#define WB_FC2 331776
#define WB_TOT 479232

// ---------------- all weights fp32 -> bf16, one launch ---------------------------
__global__ void cvt_all_kernel(const float* __restrict__ ap, const float* __restrict__ ip,
                               const float* __restrict__ qk, const float* __restrict__ op,
                               const float* __restrict__ f1, const float* __restrict__ f2,
                               __nv_bfloat16* __restrict__ d) {
    int i = blockIdx.x * 256 + threadIdx.x;
    if (i >= WB_TOT) return;
    const float* s; int off;
    if      (i < WB_IP)  { s = ap; off = WB_AP;  }
    else if (i < WB_QK)  { s = ip; off = WB_IP;  }
    else if (i < WB_OP)  { s = qk; off = WB_QK;  }
    else if (i < WB_FC1) { s = op; off = WB_OP;  }
    else if (i < WB_FC2) { s = f1; off = WB_FC1; }
    else                 { s = f2; off = WB_FC2; }
    d[i] = __float2bfloat16(s[i - off]);
}

// ---------------- RoPE tables (64 fp64 evals per block, then broadcast) ---------
__global__ void rope_init_kernel() {
    __shared__ float cs[64], sn[64];
    int p = blockIdx.x;
    int t = threadIdx.x;
    if (t < 64) {
        int j = (p < 48) ? p : p - 48;
        double theta = pow(10000.0, -(double)j / 48.0);
        double ang = (double)t * theta;
        cs[t] = (float)cos(ang);
        sn[t] = (float)sin(ang);
    }
    __syncthreads();
    bool useH = (p < 48);
    for (int i = t; i < HW; i += 256) {
        int pos = useH ? (i >> 6) : (i & 63);
        g_cos[(size_t)p * HW + i] = cs[pos];
        g_sin[(size_t)p * HW + i] = sn[pos];
    }
}

// ---------------- depthwise 3x3 ------------------------------------------------
// MODE 1: out = add + dw(in)
// MODE 2: out = silu(dw(in)) fp32 + bf16 copy
// MODE 3: outb = bf16((add + dw(in)) * gate)
template <int MODE>
__global__ __launch_bounds__(256) void dw_kernel(
    const float* __restrict__ in, const float* __restrict__ wt,
    const float* __restrict__ bs, const float* __restrict__ add,
    const float* __restrict__ gate, float* __restrict__ out,
    __nv_bfloat16* __restrict__ outb)
{
    __shared__ float sp[HW];
    int bc = blockIdx.x;
    int c  = bc % CC;
    const float* ip = in + (size_t)bc * HW;
    int t = threadIdx.x;
#pragma unroll
    for (int i = 0; i < 16; i++) sp[t + i * 256] = ip[t + i * 256];
    float w[9];
#pragma unroll
    for (int i = 0; i < 9; i++) w[i] = wt[c * 9 + i];
    float bb = bs[c];
    __syncthreads();
    for (int i = t; i < HW; i += 256) {
        int y = i >> 6, x = i & 63;
        float s = bb;
#pragma unroll
        for (int ki = 0; ki < 3; ki++) {
            int yy = y + ki - 1;
            if ((unsigned)yy < 64u) {
#pragma unroll
                for (int kj = 0; kj < 3; kj++) {
                    int xx = x + kj - 1;
                    if ((unsigned)xx < 64u) s += w[ki * 3 + kj] * sp[yy * 64 + xx];
                }
            }
        }
        size_t o = (size_t)bc * HW + i;
        if (MODE == 1) {
            out[o] = add[o] + s;
        } else if (MODE == 2) {
            float v = s / (1.f + expf(-s));
            out[o]  = v;
            outb[o] = __float2bfloat16(v);
        } else {
            outb[o] = __float2bfloat16((add[o] + s) * gate[o]);
        }
    }
}

// ---------------- LayerNorm over channels (per pixel), bf16 output -------------
__global__ __launch_bounds__(256) void ln_kernel(
    const float* __restrict__ in, const float* __restrict__ w,
    const float* __restrict__ b, __nv_bfloat16* __restrict__ out)
{
    int bi  = blockIdx.y;
    int pix = blockIdx.x * 256 + threadIdx.x;
    const float* ip = in + (size_t)bi * CC * HW + pix;
    float s = 0.f, s2 = 0.f;
#pragma unroll 4
    for (int c = 0; c < CC; c++) { float v = ip[(size_t)c * HW]; s += v; s2 += v * v; }
    float mu  = s * (1.f / CC);
    float var = s2 * (1.f / CC) - mu * mu;
    float r   = rsqrtf(var + 1e-5f);
    __nv_bfloat16* op = out + (size_t)bi * CC * HW + pix;
#pragma unroll 4
    for (int c = 0; c < CC; c++)
        op[(size_t)c * HW] = __float2bfloat16((ip[(size_t)c * HW] - mu) * r * w[c] + b[c]);
}

// ---------------- mma / ldmatrix / cp.async helpers ------------------------------
__device__ __forceinline__ unsigned pack_bf2(float lo, float hi) {
    __nv_bfloat162 h = __floats2bfloat162_rn(lo, hi);
    return *(unsigned*)&h;
}
__device__ __forceinline__ void ldm_x4(unsigned& r0, unsigned& r1, unsigned& r2,
                                       unsigned& r3, unsigned addr) {
    asm volatile("ldmatrix.sync.aligned.m8n8.x4.shared.b16 {%0,%1,%2,%3}, [%4];"
                 : "=r"(r0), "=r"(r1), "=r"(r2), "=r"(r3) : "r"(addr));
}
__device__ __forceinline__ void ldm_x4_t(unsigned& r0, unsigned& r1, unsigned& r2,
                                         unsigned& r3, unsigned addr) {
    asm volatile("ldmatrix.sync.aligned.m8n8.x4.trans.shared.b16 {%0,%1,%2,%3}, [%4];"
                 : "=r"(r0), "=r"(r1), "=r"(r2), "=r"(r3) : "r"(addr));
}
__device__ __forceinline__ void mma_bf16(float* c, const unsigned* a, const unsigned* b) {
    asm volatile(
        "mma.sync.aligned.m16n8k16.row.col.f32.bf16.bf16.f32 "
        "{%0,%1,%2,%3}, {%4,%5,%6,%7}, {%8,%9}, {%0,%1,%2,%3};"
        : "+f"(c[0]), "+f"(c[1]), "+f"(c[2]), "+f"(c[3])
        : "r"(a[0]), "r"(a[1]), "r"(a[2]), "r"(a[3]), "r"(b[0]), "r"(b[1]));
}
__device__ __forceinline__ void cpa16(unsigned smem, const void* g) {
    asm volatile("cp.async.cg.shared.global [%0], [%1], 16;" :: "r"(smem), "l"(g));
}
__device__ __forceinline__ void cpa_commit() { asm volatile("cp.async.commit_group;"); }

// ---------------- conv1x1 GEMM, bf16, warp tile 32x64, cp.async 3-stage ----------
// Block 64(M) x 128(N) x 32(K); 4 warps 2x2, warp tile 32(M)x64(N); m16n8k16.
#define AS_LD 56    // A row stride (bf16) = 112B = 7x16B
#define BS_LD 136   // B row stride (bf16) = 272B = 17x16B
#define A_ST (64 * AS_LD)
#define B_ST (32 * BS_LD)
#define NST 3
template <int ACT, bool RES, bool OUTBF>
__global__ __launch_bounds__(128) void gemm_tc(
    const __nv_bfloat16* __restrict__ in, const __nv_bfloat16* __restrict__ Wm,
    const float* __restrict__ bias, const float* __restrict__ res,
    void* __restrict__ outp, int Cin, int Cout)
{
    __shared__ __nv_bfloat16 As[NST * A_ST];
    __shared__ __nv_bfloat16 Bs[NST * B_ST];

    const int b  = blockIdx.z;
    const int mb = blockIdx.y * 64, nb = blockIdx.x * 128;
    const int t  = threadIdx.x;
    const int w  = t >> 5, lane = t & 31;
    const int g  = lane >> 2, tq = lane & 3;
    const int wm = (w >> 1) * 32, wn = (w & 1) * 64;

    const unsigned asB = (unsigned)__cvta_generic_to_shared(As);
    const unsigned bsB = (unsigned)__cvta_generic_to_shared(Bs);

    // loaders (128 threads): A 64x32 (4KB): row=t>>1, k-span (t&1)*16 (two 16B)
    const int amr = t >> 1, akk = (t & 1) * 16;
    const __nv_bfloat16* wp = Wm + (size_t)(mb + amr) * Cin + akk;
    const unsigned aDst = asB + (unsigned)((amr * AS_LD + akk) * 2);
    // B 32x128 (8KB): krow=t>>2, n-span (t&3)*32 (four 16B)
    const int bkr = t >> 2, bnn = (t & 3) * 32;
    const __nv_bfloat16* xp = in + (size_t)b * Cin * HW + (size_t)bkr * HW + nb + bnn;
    const unsigned bDst = bsB + (unsigned)((bkr * BS_LD + bnn) * 2);

    const int nchunk = Cin >> 5;

    auto issue = [&](int ch, int st) {
        const __nv_bfloat16* ws = wp + ch * 32;
        unsigned ad = aDst + (unsigned)(st * A_ST * 2);
        cpa16(ad,      ws);
        cpa16(ad + 16, ws + 8);
        const __nv_bfloat16* xs = xp + (size_t)(ch * 32) * HW;
        unsigned bd = bDst + (unsigned)(st * B_ST * 2);
        cpa16(bd,      xs);
        cpa16(bd + 16, xs + 8);
        cpa16(bd + 32, xs + 16);
        cpa16(bd + 48, xs + 24);
        cpa_commit();
    };

    // ldmatrix lane addressing
    const int aRow = (lane & 15);
    const int aKof = (lane >> 4) << 3;
    const int bKrw = (lane & 7) + (((lane >> 3) & 1) << 3);
    const int bNof = (lane >> 4) << 3;

    float c[2][8][4];
#pragma unroll
    for (int i = 0; i < 2; i++)
#pragma unroll
        for (int j = 0; j < 8; j++)
#pragma unroll
            for (int q = 0; q < 4; q++) c[i][j][q] = 0.f;

    issue(0, 0);
    issue(1, 1);

    for (int ch = 0; ch < nchunk; ch++) {
        if (ch + NST - 1 < nchunk) {
            asm volatile("cp.async.wait_group 1;");
        } else {
            asm volatile("cp.async.wait_group 0;");
        }
        __syncthreads();
        if (ch + NST - 1 < nchunk) issue(ch + NST - 1, (ch + NST - 1) % NST);

        const int st = ch % NST;
        const unsigned asS = asB + (unsigned)(st * A_ST * 2);
        const unsigned bsS = bsB + (unsigned)(st * B_ST * 2);
#pragma unroll
        for (int ks = 0; ks < 2; ks++) {
            const int k0 = ks * 16;
            unsigned a[2][4], bq[4][4];
#pragma unroll
            for (int i = 0; i < 2; i++)
                ldm_x4(a[i][0], a[i][1], a[i][2], a[i][3],
                       asS + (unsigned)(((wm + i * 16 + aRow) * AS_LD + k0 + aKof) * 2));
#pragma unroll
            for (int j2 = 0; j2 < 4; j2++)
                ldm_x4_t(bq[j2][0], bq[j2][1], bq[j2][2], bq[j2][3],
                         bsS + (unsigned)(((k0 + bKrw) * BS_LD + wn + j2 * 16 + bNof) * 2));
#pragma unroll
            for (int i = 0; i < 2; i++)
#pragma unroll
                for (int j = 0; j < 8; j++) {
                    unsigned bb[2] = { bq[j >> 1][(j & 1) * 2], bq[j >> 1][(j & 1) * 2 + 1] };
                    mma_bf16(c[i][j], a[i], bb);
                }
        }
        // no trailing sync: next iteration's __syncthreads orders overwrite
    }

    // epilogue
#pragma unroll
    for (int i = 0; i < 2; i++) {
#pragma unroll
        for (int rh = 0; rh < 2; rh++) {
            int m = mb + wm + i * 16 + g + rh * 8;
            float bi = bias[m];
            size_t rowoff = ((size_t)b * Cout + m) * HW + nb;
#pragma unroll
            for (int j = 0; j < 8; j++) {
                int n = wn + j * 8 + tq * 2;
                float v0 = c[i][j][rh * 2 + 0] + bi;
                float v1 = c[i][j][rh * 2 + 1] + bi;
                if (ACT == 1) { v0 = v0 / (1.f + expf(-v0)); v1 = v1 / (1.f + expf(-v1)); }
                if (ACT == 2) {
                    v0 = 0.5f * v0 * (1.f + erff(v0 * 0.70710678118654752f));
                    v1 = 0.5f * v1 * (1.f + erff(v1 * 0.70710678118654752f));
                }
                if (RES) {
                    const float* rp = res + rowoff + n;
                    v0 += rp[0]; v1 += rp[1];
                }
                if (OUTBF) {
                    unsigned pv = pack_bf2(v0, v1);
                    *(unsigned*)((__nv_bfloat16*)outp + rowoff + n) = pv;
                } else {
                    *(float2*)((float*)outp + rowoff + n) = make_float2(v0, v1);
                }
            }
        }
    }
}

// ---------------- elu+1, RoPE(q,k), kmean (no q buffer) -------------------------
__global__ __launch_bounds__(256) void qkpost_kernel() {
    int b = blockIdx.y, p = blockIdx.x;
    int c0 = 2 * p;
    const float* qp0 = g_qk + ((size_t)b * 2 * CC + c0) * HW;
    const float* qp1 = qp0 + HW;
    const float* kp0 = g_qk + ((size_t)b * 2 * CC + CC + c0) * HW;
    const float* kp1 = kp0 + HW;
    size_t o0 = ((size_t)b * CC + c0) * HW;
    const float* cb = g_cos + (size_t)p * HW;
    const float* sb = g_sin + (size_t)p * HW;
    float sk0 = 0.f, sk1 = 0.f;
    for (int i = threadIdx.x; i < HW; i += 256) {
        float qa = qp0[i]; qa = (qa > 0.f) ? qa + 1.f : expf(qa);
        float qb = qp1[i]; qb = (qb > 0.f) ? qb + 1.f : expf(qb);
        float ka = kp0[i]; ka = (ka > 0.f) ? ka + 1.f : expf(ka);
        float kb = kp1[i]; kb = (kb > 0.f) ? kb + 1.f : expf(kb);
        float cs = cb[i], sn = sb[i];
        g_qr[o0 + i]      = qa * cs - qb * sn;
        g_qr[o0 + HW + i] = qa * sn + qb * cs;
        g_kr[o0 + i]      = ka * cs - kb * sn;
        g_kr[o0 + HW + i] = ka * sn + kb * cs;
        sk0 += ka; sk1 += kb;
    }
    __shared__ float r0[256], r1[256];
    int t = threadIdx.x;
    r0[t] = sk0; r1[t] = sk1;
    __syncthreads();
    for (int s = 128; s > 0; s >>= 1) {
        if (t < s) { r0[t] += r0[t + s]; r1[t] += r1[t + s]; }
        __syncthreads();
    }
    if (t == 0) {
        g_km[b * CC + c0]     = r0[0] * (1.f / HW);
        g_km[b * CC + c0 + 1] = r1[0] * (1.f / HW);
    }
}

// ---------------- kv[b,h,d,e] = (1/n) sum_n k_rope[n,d] v[n,e] -----------------
__global__ __launch_bounds__(256) void kv_kernel() {
    int h = blockIdx.x, b = blockIdx.y;
    __shared__ float ks[64][36];
    __shared__ float vs[64][33];
    const float* kp = g_kr + ((size_t)b * CC + h * DD) * HW;
    const float* vp = g_t  + ((size_t)b * CC + h * DD) * HW;
    int t = threadIdx.x;
    int e = t & 31, d0 = (t >> 5) * 4;
    float a0 = 0.f, a1 = 0.f, a2 = 0.f, a3 = 0.f;
    for (int n0 = 0; n0 < HW; n0 += 64) {
#pragma unroll
        for (int l = 0; l < 8; l++) {
            int i  = t + l * 256;
            int dd = i >> 6, nn = i & 63;
            ks[nn][dd] = kp[(size_t)dd * HW + n0 + nn];
            vs[nn][dd] = vp[(size_t)dd * HW + n0 + nn];
        }
        __syncthreads();
#pragma unroll 4
        for (int nn = 0; nn < 64; nn++) {
            float4 kk = *(const float4*)&ks[nn][d0];
            float  vv = vs[nn][e];
            a0 += kk.x * vv; a1 += kk.y * vv; a2 += kk.z * vv; a3 += kk.w * vv;
        }
        __syncthreads();
    }
    float sc = 1.f / HW;
    int base = ((b * HEADS + h) * DD + d0) * DD + e;
    g_kv[base]          = a0 * sc;
    g_kv[base + DD]     = a1 * sc;
    g_kv[base + 2 * DD] = a2 * sc;
    g_kv[base + 3 * DD] = a3 * sc;
}

// ---------------- attn[b,h,n,e] = z * sum_d q_rope[n,d] kv[d,e] ----------------
// z recomputed from raw qk (elu+1 identical to qkpost) — no g_q buffer.
__global__ __launch_bounds__(256) void attn_kernel() {
    int tile = blockIdx.x, h = blockIdx.y, b = blockIdx.z;
    __shared__ float kvs[DD * DD];
    __shared__ float km[DD];
    int t = threadIdx.x;
#pragma unroll
    for (int l = 0; l < 4; l++)
        kvs[t + l * 256] = g_kv[(b * HEADS + h) * DD * DD + t + l * 256];
    if (t < DD) km[t] = g_km[b * CC + h * DD + t];
    __syncthreads();
    int pix = tile * 256 + t;
    const float* qkp = g_qk + ((size_t)b * 2 * CC + h * DD) * HW + pix;
    const float* qrp = g_qr + ((size_t)b * CC + h * DD) * HW + pix;
    float s = 0.f;
#pragma unroll
    for (int d = 0; d < DD; d++) {
        float qv = qkp[(size_t)d * HW];
        qv = (qv > 0.f) ? qv + 1.f : expf(qv);
        s += qv * km[d];
    }
    float z = 1.f / (s + 1e-6f);
    float acc[DD];
#pragma unroll
    for (int e2 = 0; e2 < DD; e2++) acc[e2] = 0.f;
#pragma unroll 8
    for (int d = 0; d < DD; d++) {
        float qd = qrp[(size_t)d * HW];
#pragma unroll
        for (int e2 = 0; e2 < DD; e2++) acc[e2] += qd * kvs[d * DD + e2];
    }
    float* op = g_attn + ((size_t)b * CC + h * DD) * HW + pix;
#pragma unroll
    for (int e2 = 0; e2 < DD; e2++) op[(size_t)e2 * HW] = acc[e2] * z;
}

// ---------------- host ----------------------------------------------------------
extern "C" void kernel_launch(void* const* d_in, const int* in_sizes, int n_in,
                              void* d_out, int out_size)
{
    const float* x      = (const float*)d_in[0];
    const float* cpe1_w = (const float*)d_in[1];
    const float* cpe1_b = (const float*)d_in[2];
    const float* n1_w   = (const float*)d_in[3];
    const float* n1_b   = (const float*)d_in[4];
    const float* ap_w   = (const float*)d_in[5];
    const float* ap_b   = (const float*)d_in[6];
    const float* ip_w   = (const float*)d_in[7];
    const float* ip_b   = (const float*)d_in[8];
    const float* dwc_w  = (const float*)d_in[9];
    const float* dwc_b  = (const float*)d_in[10];
    const float* qkw    = (const float*)d_in[11];
    const float* qkb    = (const float*)d_in[12];
    const float* lepe_w = (const float*)d_in[13];
    const float* lepe_b = (const float*)d_in[14];
    const float* op_w   = (const float*)d_in[15];
    const float* op_b   = (const float*)d_in[16];
    const float* cpe2_w = (const float*)d_in[17];
    const float* cpe2_b = (const float*)d_in[18];
    const float* n2_w   = (const float*)d_in[19];
    const float* n2_b   = (const float*)d_in[20];
    const float* fc1_w  = (const float*)d_in[21];
    const float* fc1_b  = (const float*)d_in[22];
    const float* fc2_w  = (const float*)d_in[23];
    const float* fc2_b  = (const float*)d_in[24];
    float* out = (float*)d_out;

    void* tmp;
    cudaGetSymbolAddress(&tmp, g_x);    float* px    = (float*)tmp;
    cudaGetSymbolAddress(&tmp, g_y);    __nv_bfloat16* pyb = (__nv_bfloat16*)tmp;
    cudaGetSymbolAddress(&tmp, g_act);  float* pact  = (float*)tmp;
    cudaGetSymbolAddress(&tmp, g_t);    float* pt    = (float*)tmp;
    cudaGetSymbolAddress(&tmp, g_qk);   float* pqk   = (float*)tmp;
    cudaGetSymbolAddress(&tmp, g_qr);   __nv_bfloat16* ptb = (__nv_bfloat16*)tmp;
    cudaGetSymbolAddress(&tmp, g_attn); float* pattn = (float*)tmp;
    cudaGetSymbolAddress(&tmp, g_h);    __nv_bfloat16* phb = (__nv_bfloat16*)tmp;
    cudaGetSymbolAddress(&tmp, g_wb);   __nv_bfloat16* pwb = (__nv_bfloat16*)tmp;

    // weights -> bf16 (single launch)
    cvt_all_kernel<<<(WB_TOT + 255) / 256, 256>>>(ap_w, ip_w, qkw, op_w, fc1_w, fc2_w, pwb);

    rope_init_kernel<<<NPAIR, 256>>>();

    // x = x + cpe1(x)
    dw_kernel<1><<<BB * CC, 256>>>(x, cpe1_w, cpe1_b, x, nullptr, px, nullptr);

    // y = norm1(x)  (bf16)
    ln_kernel<<<dim3(HW / 256, BB), 256>>>(px, n1_w, n1_b, pyb);

    // act_res = silu(act_proj(y));  t0 = in_proj(y)
    gemm_tc<1, false, false><<<dim3(HW / 128, CC / 64, BB), 128>>>(pyb, pwb + WB_AP, ap_b, nullptr, pact, CC, CC);
    gemm_tc<0, false, false><<<dim3(HW / 128, CC / 64, BB), 128>>>(pyb, pwb + WB_IP, ip_b, nullptr, pt,   CC, CC);

    // t = silu(dwc(t0))  -> fp32 pt + bf16 ptb
    dw_kernel<2><<<BB * CC, 256>>>(pt, dwc_w, dwc_b, nullptr, nullptr, pt, ptb);

    // qk = qk_w @ t + qk_b
    gemm_tc<0, false, false><<<dim3(HW / 128, 2 * CC / 64, BB), 128>>>(ptb, pwb + WB_QK, qkb, nullptr, pqk, CC, 2 * CC);

    // rope(q,k), kmean   (overwrites g_qr with fp32 q_rope)
    qkpost_kernel<<<dim3(NPAIR, BB), 256>>>();

    // kv, attn
    kv_kernel<<<dim3(HEADS, BB), 256>>>();
    attn_kernel<<<dim3(HW / 256, HEADS, BB), 256>>>();

    // gated = bf16((attn + lepe(v)) * act_res)
    dw_kernel<3><<<BB * CC, 256>>>(pt, lepe_w, lepe_b, pattn, pact, nullptr, phb);

    // x = x + out_proj(gated)
    gemm_tc<0, true, false><<<dim3(HW / 128, CC / 64, BB), 128>>>(phb, pwb + WB_OP, op_b, px, px, CC, CC);

    // x = x + cpe2(x)
    dw_kernel<1><<<BB * CC, 256>>>(px, cpe2_w, cpe2_b, px, nullptr, px, nullptr);

    // MLP: out = x + fc2(gelu(fc1(norm2(x))))
    ln_kernel<<<dim3(HW / 256, BB), 256>>>(px, n2_w, n2_b, pyb);
    gemm_tc<2, false, true><<<dim3(HW / 128, HID / 64, BB), 128>>>(pyb, pwb + WB_FC1, fc1_b, nullptr, phb, CC, HID);
    gemm_tc<0, true, false><<<dim3(HW / 128, CC / 64, BB), 128>>>(phb, pwb + WB_FC2, fc2_b, px, out, HID, CC);
}

// round 17
// speedup vs baseline: 2.7683x; 1.0411x over previous
#include <cuda_runtime.h>
#include <cuda_bf16.h>
#include <cstdint>
#include <math.h>

#define HW   4096
#define BB   16
#define CC   192
#define HEADS 6
#define DD   32
#define HID  768
#define NPAIR 96

// ---------------- scratch (device globals; no allocation APIs) ----------------
__device__ float g_x   [(size_t)BB*CC*HW];
__device__ float g_y   [(size_t)BB*CC*HW];
__device__ float g_act [(size_t)BB*CC*HW];
__device__ float g_t   [(size_t)BB*CC*HW];
__device__ float g_qk  [(size_t)BB*2*CC*HW];
__device__ float g_qr  [(size_t)BB*CC*HW];   // bf16 't' alias before qkpost
__device__ float g_kr  [(size_t)BB*CC*HW];
__device__ float g_attn[(size_t)BB*CC*HW];
__device__ float g_h   [(size_t)BB*HID*HW];  // bf16 gated buffer, then bf16 fc1 out
__device__ float g_kv  [BB*HEADS*DD*DD];
__device__ float g_km  [BB*CC];
__device__ float g_cos [NPAIR*64];           // compact: 64 positions per pair
__device__ float g_sin [NPAIR*64];
__device__ __nv_bfloat16 g_wb[480256];       // bf16 weight scratch

// weight offsets in g_wb
#define WB_AP  0
#define WB_IP  36864
#define WB_QK  73728
#define WB_OP  147456
#define WB_FC1 184320
#define WB_FC2 331776
#define WB_TOT 479232

// ---------------- all weights fp32 -> bf16, one launch ---------------------------
__global__ void cvt_all_kernel(const float* __restrict__ ap, const float* __restrict__ ip,
                               const float* __restrict__ qk, const float* __restrict__ op,
                               const float* __restrict__ f1, const float* __restrict__ f2,
                               __nv_bfloat16* __restrict__ d) {
    int i = blockIdx.x * 256 + threadIdx.x;
    if (i >= WB_TOT) return;
    const float* s; int off;
    if      (i < WB_IP)  { s = ap; off = WB_AP;  }
    else if (i < WB_QK)  { s = ip; off = WB_IP;  }
    else if (i < WB_OP)  { s = qk; off = WB_QK;  }
    else if (i < WB_FC1) { s = op; off = WB_OP;  }
    else if (i < WB_FC2) { s = f1; off = WB_FC1; }
    else                 { s = f2; off = WB_FC2; }
    d[i] = __float2bfloat16(s[i - off]);
}

// ---------------- RoPE tables, compact [NPAIR][64] ------------------------------
__global__ void rope_init_kernel() {
    int idx = blockIdx.x * 256 + threadIdx.x;
    if (idx >= NPAIR * 64) return;
    int p = idx >> 6, pos = idx & 63;
    int j = (p < 48) ? p : p - 48;
    double theta = pow(10000.0, -(double)j / 48.0);
    double ang = (double)pos * theta;
    g_cos[idx] = (float)cos(ang);
    g_sin[idx] = (float)sin(ang);
}

// ---------------- depthwise 3x3 ------------------------------------------------
// MODE 1: out = add + dw(in)
// MODE 2: out = silu(dw(in)) fp32 + bf16 copy
// MODE 3: outb = bf16((add + dw(in)) * gate)
template <int MODE>
__global__ __launch_bounds__(256) void dw_kernel(
    const float* __restrict__ in, const float* __restrict__ wt,
    const float* __restrict__ bs, const float* __restrict__ add,
    const float* __restrict__ gate, float* __restrict__ out,
    __nv_bfloat16* __restrict__ outb)
{
    __shared__ float sp[HW];
    int bc = blockIdx.x;
    int c  = bc % CC;
    const float* ip = in + (size_t)bc * HW;
    int t = threadIdx.x;
#pragma unroll
    for (int i = 0; i < 16; i++) sp[t + i * 256] = ip[t + i * 256];
    float w[9];
#pragma unroll
    for (int i = 0; i < 9; i++) w[i] = wt[c * 9 + i];
    float bb = bs[c];
    __syncthreads();
    for (int i = t; i < HW; i += 256) {
        int y = i >> 6, x = i & 63;
        float s = bb;
#pragma unroll
        for (int ki = 0; ki < 3; ki++) {
            int yy = y + ki - 1;
            if ((unsigned)yy < 64u) {
#pragma unroll
                for (int kj = 0; kj < 3; kj++) {
                    int xx = x + kj - 1;
                    if ((unsigned)xx < 64u) s += w[ki * 3 + kj] * sp[yy * 64 + xx];
                }
            }
        }
        size_t o = (size_t)bc * HW + i;
        if (MODE == 1) {
            out[o] = add[o] + s;
        } else if (MODE == 2) {
            float v = s / (1.f + expf(-s));
            out[o]  = v;
            outb[o] = __float2bfloat16(v);
        } else {
            outb[o] = __float2bfloat16((add[o] + s) * gate[o]);
        }
    }
}

// ---------------- LayerNorm: 4 threads/pixel, values cached in registers --------
__global__ __launch_bounds__(256) void ln_kernel(
    const float* __restrict__ in, const float* __restrict__ w,
    const float* __restrict__ b, __nv_bfloat16* __restrict__ out)
{
    __shared__ float sw[CC], sb[CC];
    int t = threadIdx.x;
    if (t < CC) { sw[t] = w[t]; sb[t] = b[t]; }
    __syncthreads();
    int bi   = blockIdx.y;
    int pix  = blockIdx.x * 64 + (t >> 2);
    int part = t & 3;                       // 48 channels per thread
    const float* ip = in + ((size_t)bi * CC + part * 48) * HW + pix;
    float v[48];
    float s = 0.f, s2 = 0.f;
#pragma unroll
    for (int i = 0; i < 48; i++) {
        v[i] = ip[(size_t)i * HW];
        s += v[i]; s2 += v[i] * v[i];
    }
    s  += __shfl_xor_sync(0xffffffffu, s, 1);
    s2 += __shfl_xor_sync(0xffffffffu, s2, 1);
    s  += __shfl_xor_sync(0xffffffffu, s, 2);
    s2 += __shfl_xor_sync(0xffffffffu, s2, 2);
    float mu  = s * (1.f / CC);
    float var = s2 * (1.f / CC) - mu * mu;
    float r   = rsqrtf(var + 1e-5f);
    __nv_bfloat16* op = out + ((size_t)bi * CC + part * 48) * HW + pix;
#pragma unroll
    for (int i = 0; i < 48; i++)
        op[(size_t)i * HW] =
            __float2bfloat16((v[i] - mu) * r * sw[part * 48 + i] + sb[part * 48 + i]);
}

// ---------------- mma / ldmatrix / cp.async helpers ------------------------------
__device__ __forceinline__ unsigned pack_bf2(float lo, float hi) {
    __nv_bfloat162 h = __floats2bfloat162_rn(lo, hi);
    return *(unsigned*)&h;
}
__device__ __forceinline__ void ldm_x4(unsigned& r0, unsigned& r1, unsigned& r2,
                                       unsigned& r3, unsigned addr) {
    asm volatile("ldmatrix.sync.aligned.m8n8.x4.shared.b16 {%0,%1,%2,%3}, [%4];"
                 : "=r"(r0), "=r"(r1), "=r"(r2), "=r"(r3) : "r"(addr));
}
__device__ __forceinline__ void ldm_x4_t(unsigned& r0, unsigned& r1, unsigned& r2,
                                         unsigned& r3, unsigned addr) {
    asm volatile("ldmatrix.sync.aligned.m8n8.x4.trans.shared.b16 {%0,%1,%2,%3}, [%4];"
                 : "=r"(r0), "=r"(r1), "=r"(r2), "=r"(r3) : "r"(addr));
}
__device__ __forceinline__ void mma_bf16(float* c, const unsigned* a, const unsigned* b) {
    asm volatile(
        "mma.sync.aligned.m16n8k16.row.col.f32.bf16.bf16.f32 "
        "{%0,%1,%2,%3}, {%4,%5,%6,%7}, {%8,%9}, {%0,%1,%2,%3};"
        : "+f"(c[0]), "+f"(c[1]), "+f"(c[2]), "+f"(c[3])
        : "r"(a[0]), "r"(a[1]), "r"(a[2]), "r"(a[3]), "r"(b[0]), "r"(b[1]));
}
__device__ __forceinline__ void cpa16(unsigned smem, const void* g) {
    asm volatile("cp.async.cg.shared.global [%0], [%1], 16;" :: "r"(smem), "l"(g));
}
__device__ __forceinline__ void cpa_commit() { asm volatile("cp.async.commit_group;"); }

// ---------------- conv1x1 GEMM, bf16, warp tile 32x64, cp.async 3-stage ----------
// Block 64(M) x 128(N) x 32(K); 4 warps 2x2, warp tile 32(M)x64(N); m16n8k16.
#define AS_LD 56    // A row stride (bf16) = 112B = 7x16B
#define BS_LD 136   // B row stride (bf16) = 272B = 17x16B
#define A_ST (64 * AS_LD)
#define B_ST (32 * BS_LD)
#define NST 3
template <int ACT, bool RES, bool OUTBF>
__global__ __launch_bounds__(128) void gemm_tc(
    const __nv_bfloat16* __restrict__ in, const __nv_bfloat16* __restrict__ Wm,
    const float* __restrict__ bias, const float* __restrict__ res,
    void* __restrict__ outp, int Cin, int Cout)
{
    __shared__ __nv_bfloat16 As[NST * A_ST];
    __shared__ __nv_bfloat16 Bs[NST * B_ST];

    const int b  = blockIdx.z;
    const int mb = blockIdx.y * 64, nb = blockIdx.x * 128;
    const int t  = threadIdx.x;
    const int w  = t >> 5, lane = t & 31;
    const int g  = lane >> 2, tq = lane & 3;
    const int wm = (w >> 1) * 32, wn = (w & 1) * 64;

    const unsigned asB = (unsigned)__cvta_generic_to_shared(As);
    const unsigned bsB = (unsigned)__cvta_generic_to_shared(Bs);

    const int amr = t >> 1, akk = (t & 1) * 16;
    const __nv_bfloat16* wp = Wm + (size_t)(mb + amr) * Cin + akk;
    const unsigned aDst = asB + (unsigned)((amr * AS_LD + akk) * 2);
    const int bkr = t >> 2, bnn = (t & 3) * 32;
    const __nv_bfloat16* xp = in + (size_t)b * Cin * HW + (size_t)bkr * HW + nb + bnn;
    const unsigned bDst = bsB + (unsigned)((bkr * BS_LD + bnn) * 2);

    const int nchunk = Cin >> 5;

    auto issue = [&](int ch, int st) {
        const __nv_bfloat16* ws = wp + ch * 32;
        unsigned ad = aDst + (unsigned)(st * A_ST * 2);
        cpa16(ad,      ws);
        cpa16(ad + 16, ws + 8);
        const __nv_bfloat16* xs = xp + (size_t)(ch * 32) * HW;
        unsigned bd = bDst + (unsigned)(st * B_ST * 2);
        cpa16(bd,      xs);
        cpa16(bd + 16, xs + 8);
        cpa16(bd + 32, xs + 16);
        cpa16(bd + 48, xs + 24);
        cpa_commit();
    };

    const int aRow = (lane & 15);
    const int aKof = (lane >> 4) << 3;
    const int bKrw = (lane & 7) + (((lane >> 3) & 1) << 3);
    const int bNof = (lane >> 4) << 3;

    float c[2][8][4];
#pragma unroll
    for (int i = 0; i < 2; i++)
#pragma unroll
        for (int j = 0; j < 8; j++)
#pragma unroll
            for (int q = 0; q < 4; q++) c[i][j][q] = 0.f;

    issue(0, 0);
    issue(1, 1);

    for (int ch = 0; ch < nchunk; ch++) {
        if (ch + NST - 1 < nchunk) {
            asm volatile("cp.async.wait_group 1;");
        } else {
            asm volatile("cp.async.wait_group 0;");
        }
        __syncthreads();
        if (ch + NST - 1 < nchunk) issue(ch + NST - 1, (ch + NST - 1) % NST);

        const int st = ch % NST;
        const unsigned asS = asB + (unsigned)(st * A_ST * 2);
        const unsigned bsS = bsB + (unsigned)(st * B_ST * 2);
#pragma unroll
        for (int ks = 0; ks < 2; ks++) {
            const int k0 = ks * 16;
            unsigned a[2][4], bq[4][4];
#pragma unroll
            for (int i = 0; i < 2; i++)
                ldm_x4(a[i][0], a[i][1], a[i][2], a[i][3],
                       asS + (unsigned)(((wm + i * 16 + aRow) * AS_LD + k0 + aKof) * 2));
#pragma unroll
            for (int j2 = 0; j2 < 4; j2++)
                ldm_x4_t(bq[j2][0], bq[j2][1], bq[j2][2], bq[j2][3],
                         bsS + (unsigned)(((k0 + bKrw) * BS_LD + wn + j2 * 16 + bNof) * 2));
#pragma unroll
            for (int i = 0; i < 2; i++)
#pragma unroll
                for (int j = 0; j < 8; j++) {
                    unsigned bb[2] = { bq[j >> 1][(j & 1) * 2], bq[j >> 1][(j & 1) * 2 + 1] };
                    mma_bf16(c[i][j], a[i], bb);
                }
        }
    }

    // epilogue
#pragma unroll
    for (int i = 0; i < 2; i++) {
#pragma unroll
        for (int rh = 0; rh < 2; rh++) {
            int m = mb + wm + i * 16 + g + rh * 8;
            float bi = bias[m];
            size_t rowoff = ((size_t)b * Cout + m) * HW + nb;
#pragma unroll
            for (int j = 0; j < 8; j++) {
                int n = wn + j * 8 + tq * 2;
                float v0 = c[i][j][rh * 2 + 0] + bi;
                float v1 = c[i][j][rh * 2 + 1] + bi;
                if (ACT == 1) { v0 = v0 / (1.f + expf(-v0)); v1 = v1 / (1.f + expf(-v1)); }
                if (ACT == 2) {
                    v0 = 0.5f * v0 * (1.f + erff(v0 * 0.70710678118654752f));
                    v1 = 0.5f * v1 * (1.f + erff(v1 * 0.70710678118654752f));
                }
                if (RES) {
                    const float* rp = res + rowoff + n;
                    v0 += rp[0]; v1 += rp[1];
                }
                if (OUTBF) {
                    unsigned pv = pack_bf2(v0, v1);
                    *(unsigned*)((__nv_bfloat16*)outp + rowoff + n) = pv;
                } else {
                    *(float2*)((float*)outp + rowoff + n) = make_float2(v0, v1);
                }
            }
        }
    }
}

// ---------------- elu+1, RoPE(q,k), kmean (compact tables in smem) --------------
__global__ __launch_bounds__(256) void qkpost_kernel() {
    __shared__ float cs[64], sn[64];
    int b = blockIdx.y, p = blockIdx.x;
    int t = threadIdx.x;
    if (t < 64) { cs[t] = g_cos[p * 64 + t]; sn[t] = g_sin[p * 64 + t]; }
    __syncthreads();
    bool useH = (p < 48);
    int c0 = 2 * p;
    const float* qp0 = g_qk + ((size_t)b * 2 * CC + c0) * HW;
    const float* qp1 = qp0 + HW;
    const float* kp0 = g_qk + ((size_t)b * 2 * CC + CC + c0) * HW;
    const float* kp1 = kp0 + HW;
    size_t o0 = ((size_t)b * CC + c0) * HW;
    float sk0 = 0.f, sk1 = 0.f;
    for (int i = t; i < HW; i += 256) {
        float qa = qp0[i]; qa = (qa > 0.f) ? qa + 1.f : expf(qa);
        float qb = qp1[i]; qb = (qb > 0.f) ? qb + 1.f : expf(qb);
        float ka = kp0[i]; ka = (ka > 0.f) ? ka + 1.f : expf(ka);
        float kb = kp1[i]; kb = (kb > 0.f) ? kb + 1.f : expf(kb);
        int pos = useH ? (i >> 6) : (i & 63);
        float cv = cs[pos], sv = sn[pos];
        g_qr[o0 + i]      = qa * cv - qb * sv;
        g_qr[o0 + HW + i] = qa * sv + qb * cv;
        g_kr[o0 + i]      = ka * cv - kb * sv;
        g_kr[o0 + HW + i] = ka * sv + kb * cv;
        sk0 += ka; sk1 += kb;
    }
    __shared__ float r0[256], r1[256];
    r0[t] = sk0; r1[t] = sk1;
    __syncthreads();
    for (int s = 128; s > 0; s >>= 1) {
        if (t < s) { r0[t] += r0[t + s]; r1[t] += r1[t + s]; }
        __syncthreads();
    }
    if (t == 0) {
        g_km[b * CC + c0]     = r0[0] * (1.f / HW);
        g_km[b * CC + c0 + 1] = r1[0] * (1.f / HW);
    }
}

// ---------------- kv[b,h,d,e] = (1/n) sum_n k_rope[n,d] v[n,e] -----------------
__global__ __launch_bounds__(256) void kv_kernel() {
    int h = blockIdx.x, b = blockIdx.y;
    __shared__ float ks[64][36];
    __shared__ float vs[64][33];
    const float* kp = g_kr + ((size_t)b * CC + h * DD) * HW;
    const float* vp = g_t  + ((size_t)b * CC + h * DD) * HW;
    int t = threadIdx.x;
    int e = t & 31, d0 = (t >> 5) * 4;
    float a0 = 0.f, a1 = 0.f, a2 = 0.f, a3 = 0.f;
    for (int n0 = 0; n0 < HW; n0 += 64) {
#pragma unroll
        for (int l = 0; l < 8; l++) {
            int i  = t + l * 256;
            int dd = i >> 6, nn = i & 63;
            ks[nn][dd] = kp[(size_t)dd * HW + n0 + nn];
            vs[nn][dd] = vp[(size_t)dd * HW + n0 + nn];
        }
        __syncthreads();
#pragma unroll 4
        for (int nn = 0; nn < 64; nn++) {
            float4 kk = *(const float4*)&ks[nn][d0];
            float  vv = vs[nn][e];
            a0 += kk.x * vv; a1 += kk.y * vv; a2 += kk.z * vv; a3 += kk.w * vv;
        }
        __syncthreads();
    }
    float sc = 1.f / HW;
    int base = ((b * HEADS + h) * DD + d0) * DD + e;
    g_kv[base]          = a0 * sc;
    g_kv[base + DD]     = a1 * sc;
    g_kv[base + 2 * DD] = a2 * sc;
    g_kv[base + 3 * DD] = a3 * sc;
}

// ---------------- attn[b,h,n,e] = z * sum_d q_rope[n,d] kv[d,e] ----------------
__global__ __launch_bounds__(256) void attn_kernel() {
    int tile = blockIdx.x, h = blockIdx.y, b = blockIdx.z;
    __shared__ float kvs[DD * DD];
    __shared__ float km[DD];
    int t = threadIdx.x;
#pragma unroll
    for (int l = 0; l < 4; l++)
        kvs[t + l * 256] = g_kv[(b * HEADS + h) * DD * DD + t + l * 256];
    if (t < DD) km[t] = g_km[b * CC + h * DD + t];
    __syncthreads();
    int pix = tile * 256 + t;
    const float* qkp = g_qk + ((size_t)b * 2 * CC + h * DD) * HW + pix;
    const float* qrp = g_qr + ((size_t)b * CC + h * DD) * HW + pix;
    float s = 0.f;
#pragma unroll
    for (int d = 0; d < DD; d++) {
        float qv = qkp[(size_t)d * HW];
        qv = (qv > 0.f) ? qv + 1.f : expf(qv);
        s += qv * km[d];
    }
    float z = 1.f / (s + 1e-6f);
    float acc[DD];
#pragma unroll
    for (int e2 = 0; e2 < DD; e2++) acc[e2] = 0.f;
#pragma unroll 8
    for (int d = 0; d < DD; d++) {
        float qd = qrp[(size_t)d * HW];
#pragma unroll
        for (int e2 = 0; e2 < DD; e2++) acc[e2] += qd * kvs[d * DD + e2];
    }
    float* op = g_attn + ((size_t)b * CC + h * DD) * HW + pix;
#pragma unroll
    for (int e2 = 0; e2 < DD; e2++) op[(size_t)e2 * HW] = acc[e2] * z;
}

// ---------------- host ----------------------------------------------------------
extern "C" void kernel_launch(void* const* d_in, const int* in_sizes, int n_in,
                              void* d_out, int out_size)
{
    const float* x      = (const float*)d_in[0];
    const float* cpe1_w = (const float*)d_in[1];
    const float* cpe1_b = (const float*)d_in[2];
    const float* n1_w   = (const float*)d_in[3];
    const float* n1_b   = (const float*)d_in[4];
    const float* ap_w   = (const float*)d_in[5];
    const float* ap_b   = (const float*)d_in[6];
    const float* ip_w   = (const float*)d_in[7];
    const float* ip_b   = (const float*)d_in[8];
    const float* dwc_w  = (const float*)d_in[9];
    const float* dwc_b  = (const float*)d_in[10];
    const float* qkw    = (const float*)d_in[11];
    const float* qkb    = (const float*)d_in[12];
    const float* lepe_w = (const float*)d_in[13];
    const float* lepe_b = (const float*)d_in[14];
    const float* op_w   = (const float*)d_in[15];
    const float* op_b   = (const float*)d_in[16];
    const float* cpe2_w = (const float*)d_in[17];
    const float* cpe2_b = (const float*)d_in[18];
    const float* n2_w   = (const float*)d_in[19];
    const float* n2_b   = (const float*)d_in[20];
    const float* fc1_w  = (const float*)d_in[21];
    const float* fc1_b  = (const float*)d_in[22];
    const float* fc2_w  = (const float*)d_in[23];
    const float* fc2_b  = (const float*)d_in[24];
    float* out = (float*)d_out;

    void* tmp;
    cudaGetSymbolAddress(&tmp, g_x);    float* px    = (float*)tmp;
    cudaGetSymbolAddress(&tmp, g_y);    __nv_bfloat16* pyb = (__nv_bfloat16*)tmp;
    cudaGetSymbolAddress(&tmp, g_act);  float* pact  = (float*)tmp;
    cudaGetSymbolAddress(&tmp, g_t);    float* pt    = (float*)tmp;
    cudaGetSymbolAddress(&tmp, g_qk);   float* pqk   = (float*)tmp;
    cudaGetSymbolAddress(&tmp, g_qr);   __nv_bfloat16* ptb = (__nv_bfloat16*)tmp;
    cudaGetSymbolAddress(&tmp, g_attn); float* pattn = (float*)tmp;
    cudaGetSymbolAddress(&tmp, g_h);    __nv_bfloat16* phb = (__nv_bfloat16*)tmp;
    cudaGetSymbolAddress(&tmp, g_wb);   __nv_bfloat16* pwb = (__nv_bfloat16*)tmp;

    // weights -> bf16 (single launch); compact rope tables
    cvt_all_kernel<<<(WB_TOT + 255) / 256, 256>>>(ap_w, ip_w, qkw, op_w, fc1_w, fc2_w, pwb);
    rope_init_kernel<<<(NPAIR * 64 + 255) / 256, 256>>>();

    // x = x + cpe1(x)
    dw_kernel<1><<<BB * CC, 256>>>(x, cpe1_w, cpe1_b, x, nullptr, px, nullptr);

    // y = norm1(x)  (bf16)
    ln_kernel<<<dim3(HW / 64, BB), 256>>>(px, n1_w, n1_b, pyb);

    // act_res = silu(act_proj(y));  t0 = in_proj(y)
    gemm_tc<1, false, false><<<dim3(HW / 128, CC / 64, BB), 128>>>(pyb, pwb + WB_AP, ap_b, nullptr, pact, CC, CC);
    gemm_tc<0, false, false><<<dim3(HW / 128, CC / 64, BB), 128>>>(pyb, pwb + WB_IP, ip_b, nullptr, pt,   CC, CC);

    // t = silu(dwc(t0))  -> fp32 pt + bf16 ptb
    dw_kernel<2><<<BB * CC, 256>>>(pt, dwc_w, dwc_b, nullptr, nullptr, pt, ptb);

    // qk = qk_w @ t + qk_b
    gemm_tc<0, false, false><<<dim3(HW / 128, 2 * CC / 64, BB), 128>>>(ptb, pwb + WB_QK, qkb, nullptr, pqk, CC, 2 * CC);

    // rope(q,k), kmean   (overwrites g_qr with fp32 q_rope)
    qkpost_kernel<<<dim3(NPAIR, BB), 256>>>();

    // kv, attn
    kv_kernel<<<dim3(HEADS, BB), 256>>>();
    attn_kernel<<<dim3(HW / 256, HEADS, BB), 256>>>();

    // gated = bf16((attn + lepe(v)) * act_res)
    dw_kernel<3><<<BB * CC, 256>>>(pt, lepe_w, lepe_b, pattn, pact, nullptr, phb);

    // x = x + out_proj(gated)
    gemm_tc<0, true, false><<<dim3(HW / 128, CC / 64, BB), 128>>>(phb, pwb + WB_OP, op_b, px, px, CC, CC);

    // x = x + cpe2(x)
    dw_kernel<1><<<BB * CC, 256>>>(px, cpe2_w, cpe2_b, px, nullptr, px, nullptr);

    // MLP: out = x + fc2(gelu(fc1(norm2(x))))
    ln_kernel<<<dim3(HW / 64, BB), 256>>>(px, n2_w, n2_b, pyb);
    gemm_tc<2, false, true><<<dim3(HW / 128, HID / 64, BB), 128>>>(pyb, pwb + WB_FC1, fc1_b, nullptr, phb, CC, HID);
    gemm_tc<0, true, false><<<dim3(HW / 128, CC / 64, BB), 128>>>(phb, pwb + WB_FC2, fc2_b, px, out, HID, CC);
}